// round 13
// baseline (speedup 1.0000x reference)
#include <cuda_runtime.h>
#include <cstdint>

// Problem constants
#define BB     4
#define NSEQ   2048
#define EE     1600
#define RR     448
#define HH     512
#define NHEAD  4
#define DHEAD  128
#define PP     2
#define FFD    2048
#define MTOK   (BB*NSEQ)
#define QKVLD  1536

// -------- scratch (device globals; no allocation allowed) --------
__device__ float g_x[(size_t)BB*NSEQ*HH];
__device__ float g_qkv[(size_t)BB*NSEQ*QKVLD];
__device__ float g_q[(size_t)BB*NSEQ*HH];
__device__ float g_k[(size_t)BB*NSEQ*HH];
__device__ float g_t[(size_t)BB*NSEQ*HH];
__device__ float g_f[(size_t)BB*NSEQ*FFD];
__device__ float g_wt[(size_t)PP*3145728];            // transposed weights
__device__ float g_bcat[PP*QKVLD];                    // concat qkv bias

// ---------------- helpers ----------------
__device__ __forceinline__ unsigned f2tf32(float x) {
    unsigned r; asm("cvt.rna.tf32.f32 %0, %1;" : "=r"(r) : "f"(x)); return r;
}
__device__ __forceinline__ float rnd32(float x) {
    return __uint_as_float(f2tf32(x));
}
__device__ __forceinline__ uint32_t smem_u32(const void* p) {
    uint32_t a;
    asm("{ .reg .u64 t; cvta.to.shared.u64 t, %1; cvt.u32.u64 %0, t; }" : "=r"(a) : "l"(p));
    return a;
}
__device__ __forceinline__ unsigned lds32(uint32_t a) {
    unsigned v; asm("ld.shared.b32 %0, [%1];" : "=r"(v) : "r"(a)); return v;
}
// ldmatrix x4: four 8x8 b16 tiles -> 4 regs/lane (tf32 fragment gather)
__device__ __forceinline__ void ldsm4(unsigned* r, uint32_t a) {
    asm volatile("ldmatrix.sync.aligned.m8n8.x4.shared.b16 {%0,%1,%2,%3}, [%4];"
                 : "=r"(r[0]), "=r"(r[1]), "=r"(r[2]), "=r"(r[3]) : "r"(a));
}
#define SWZ128(o) ((o) ^ (((o) >> 3) & 0x70))

__device__ __forceinline__ void mma_tf32(float* d, const unsigned* a,
                                         unsigned b0, unsigned b1) {
    asm volatile("mma.sync.aligned.m16n8k8.row.col.f32.tf32.tf32.f32 "
                 "{%0,%1,%2,%3}, {%4,%5,%6,%7}, {%8,%9}, {%0,%1,%2,%3};"
                 : "+f"(d[0]), "+f"(d[1]), "+f"(d[2]), "+f"(d[3])
                 : "r"(a[0]), "r"(a[1]), "r"(a[2]), "r"(a[3]),
                   "r"(b0), "r"(b1));
}

#define CP16(d, s)   asm volatile("cp.async.cg.shared.global [%0], [%1], 16;" :: "r"(d), "l"(s))
#define CP_COMMIT()  asm volatile("cp.async.commit_group;")
#define CP_WAIT(n)   asm volatile("cp.async.wait_group %0;" :: "n"(n))

#define STAGE_SZ   32768     // GEMM: A(16KB, 128x32 f32 SW128) + B(16KB)
#define SMEM_DYN   (2*STAGE_SZ)

// ======== pipelined tf32 mma.sync GEMM, 128x128 tile + ldmatrix ========
// 256 threads, warp grid 2(m) x 4(n), warp tile 64x32, BK=32.
// __launch_bounds__(256,2): <=128 regs -> 2 CTAs/SM.
// All 24 swizzled fragment addresses hoisted out of the mainloop.
template<int EPI>   // 0 none, 1 +bias, 2 +bias+prelu
__global__ __launch_bounds__(256, 2)
void k_mm(const float* __restrict__ A, int lda,
          const float* __restrict__ B, int ldb,
          float* __restrict__ C, int ldc, int K,
          const float* __restrict__ bias,
          const float* __restrict__ alpha)
{
    extern __shared__ __align__(1024) char dynsmem[];
    const uint32_t sb = smem_u32(dynsmem);
    const int tid = threadIdx.x, lane = tid & 31, wid = tid >> 5;
    const int wm = wid & 1, wn = wid >> 1;
    const int row0 = blockIdx.y * 128, col0 = blockIdx.x * 128;

    auto copy_tile = [&](int it, int s) {
        const uint32_t a_s = sb + s * STAGE_SZ;
        const uint32_t b_s = a_s + 16384;
        const int k0 = it << 5;
#pragma unroll
        for (int u = 0; u < 4; u++) {
            int idx = tid + 256 * u;
            int r = idx >> 3, c16 = (idx & 7) << 4;
            uint32_t sw = SWZ128((r << 7) + c16);
            CP16(a_s + sw, A + (size_t)(row0 + r) * lda + k0 + (c16 >> 2));
            CP16(b_s + sw, B + (size_t)(col0 + r) * ldb + k0 + (c16 >> 2));
        }
    };

    float acc[4][4][4];
#pragma unroll
    for (int t = 0; t < 4; t++)
#pragma unroll
        for (int nt = 0; nt < 4; nt++)
#pragma unroll
            for (int r = 0; r < 4; r++) acc[t][nt][r] = 0.f;

    const int T = K >> 5;
    copy_tile(0, 0);
    CP_COMMIT();

    // ldmatrix lane addressing: lanes 0-15 -> rows (lane&15), tf32 cols +0..3;
    // lanes 16-31 -> same rows, cols +4..7.
    const int li = lane & 15;
    const int chb = ((lane >> 4) << 4);       // byte offset of col-half

    // hoist: 16 A-addrs + 8 B-addrs (stage 0), one IADD per use in loop
    uint32_t aAd[4][4], bAd[2][4];
#pragma unroll
    for (int t = 0; t < 4; t++) {
        const uint32_t base = sb + ((wm * 64 + t * 16 + li) << 7);
#pragma unroll
        for (int k8 = 0; k8 < 4; k8++)
            aAd[t][k8] = SWZ128(base + (k8 << 5) + chb);
    }
#pragma unroll
    for (int p = 0; p < 2; p++) {
        const uint32_t base = sb + 16384 + ((wn * 32 + p * 16 + li) << 7);
#pragma unroll
        for (int k8 = 0; k8 < 4; k8++)
            bAd[p][k8] = SWZ128(base + (k8 << 5) + chb);
    }

    for (int it = 0; it < T; it++) {
        const int s = it & 1;
        if (it + 1 < T) {
            copy_tile(it + 1, s ^ 1);
            CP_COMMIT();
            CP_WAIT(1);
        } else {
            CP_WAIT(0);
        }
        __syncthreads();

        const uint32_t sOff = s * STAGE_SZ;
#pragma unroll
        for (int k8 = 0; k8 < 4; k8++) {
            unsigned af[4][4], bt[2][4];
#pragma unroll
            for (int t = 0; t < 4; t++)
                ldsm4(af[t], aAd[t][k8] + sOff);
#pragma unroll
            for (int p = 0; p < 2; p++)
                ldsm4(bt[p], bAd[p][k8] + sOff);
#pragma unroll
            for (int t = 0; t < 4; t++) {
                mma_tf32(acc[t][0], af[t], bt[0][0], bt[0][2]);
                mma_tf32(acc[t][1], af[t], bt[0][1], bt[0][3]);
                mma_tf32(acc[t][2], af[t], bt[1][0], bt[1][2]);
                mma_tf32(acc[t][3], af[t], bt[1][1], bt[1][3]);
            }
        }
        __syncthreads();
    }

    const int r = lane >> 2;
    const int cq = (lane & 3) << 1;
#pragma unroll
    for (int t = 0; t < 4; t++) {
        const int row = row0 + wm * 64 + t * 16 + r;
#pragma unroll
        for (int nt = 0; nt < 4; nt++) {
            const int col = col0 + wn * 32 + nt * 8 + cq;
            float2 v0 = make_float2(acc[t][nt][0], acc[t][nt][1]);
            float2 v1 = make_float2(acc[t][nt][2], acc[t][nt][3]);
            if (EPI == 1 || EPI == 2) {
                float b0 = bias[col], b1 = bias[col + 1];
                v0.x += b0; v0.y += b1; v1.x += b0; v1.y += b1;
            }
            if (EPI == 2) {
                float a0 = alpha[col], a1 = alpha[col + 1];
                v0.x = (v0.x >= 0.f) ? v0.x : a0 * v0.x;
                v0.y = (v0.y >= 0.f) ? v0.y : a1 * v0.y;
                v1.x = (v1.x >= 0.f) ? v1.x : a0 * v1.x;
                v1.y = (v1.y >= 0.f) ? v1.y : a1 * v1.y;
            }
            v0.x = rnd32(v0.x); v0.y = rnd32(v0.y);
            v1.x = rnd32(v1.x); v1.y = rnd32(v1.y);
            *(float2*)(C + (size_t)row * ldc + col)       = v0;
            *(float2*)(C + (size_t)(row + 8) * ldc + col) = v1;
        }
    }
}

// ======== fused flash attention (validated; QKV from g_qkv) ========
#define QS_OFF  0u
#define KS_OFF  8448u
#define KS_LEN  4224u
#define VS_OFF  16896u
#define VS_LEN  4352u
#define PS_OFF  25600u
#define FLASH_SMEM  111616   // bytes -> 2 CTAs/SM

__global__ __launch_bounds__(128)
void k_flash(const int* __restrict__ adjs) {
    extern __shared__ __align__(16) char dynsmem[];
    float* smemf = (float*)dynsmem;
    const uint32_t sb = smem_u32(dynsmem);
    const int tid = threadIdx.x, lane = tid & 31, wid = tid >> 5;
    const int fr = lane >> 2, fc = lane & 3;
    const int z = blockIdx.y, b = z >> 2, h = z & 3;
    const int q0 = blockIdx.x * 64;
    const float* Qg = g_qkv + ((size_t)b * NSEQ + q0) * QKVLD + h * DHEAD;
    const float* Kg = g_qkv + (size_t)b * NSEQ * QKVLD + 512 + h * DHEAD;
    const float* Vg = g_qkv + (size_t)b * NSEQ * QKVLD + 1024 + h * DHEAD;
    const int* adj = adjs + (size_t)b * NSEQ * NSEQ;
    const int r_lo = wid * 16 + fr;
    float* Pw = smemf + PS_OFF + wid * 576;   // [16][36] per warp

#pragma unroll
    for (int u = 0; u < 16; u++) {
        int idx = tid + 128 * u;
        int r = idx >> 5, cg = idx & 31;
        float4 v = *(const float4*)(Qg + (size_t)r * QKVLD + 4 * cg);
        *(float4*)(smemf + QS_OFF + r * 132 + 4 * cg) = v;
    }

    auto stage_kv = [&](int it, int s) {
        const int k0 = it << 5;
        const uint32_t kO = KS_OFF + s * KS_LEN;
        const uint32_t vO = VS_OFF + s * VS_LEN;
#pragma unroll
        for (int u = 0; u < 8; u++) {
            int idx = tid + 128 * u;
            int r = idx >> 5, cg = idx & 31;
            CP16(sb + 4 * (kO + r * 132 + 4 * cg), Kg + (size_t)(k0 + r) * QKVLD + 4 * cg);
            CP16(sb + 4 * (vO + r * 136 + 4 * cg), Vg + (size_t)(k0 + r) * QKVLD + 4 * cg);
        }
    };

    float acc_o[16][4];
#pragma unroll
    for (int nt = 0; nt < 16; nt++)
#pragma unroll
        for (int j = 0; j < 4; j++) acc_o[nt][j] = 0.f;
    float m0 = -3.4e38f, m1 = -3.4e38f, l0 = 0.f, l1 = 0.f;
    const float rs = 0.08838834764831845f;

    const int T = NSEQ / 32;
    stage_kv(0, 0);
    CP_COMMIT();

    for (int it = 0; it < T; it++) {
        const int s = it & 1;
        if (it + 1 < T) {
            stage_kv(it + 1, s ^ 1);
            CP_COMMIT();
            CP_WAIT(1);
        } else {
            CP_WAIT(0);
        }
        __syncthreads();
        const uint32_t kO = KS_OFF + s * KS_LEN;
        const uint32_t vO = VS_OFF + s * VS_LEN;

        float s_[4][4];
#pragma unroll
        for (int nt = 0; nt < 4; nt++)
#pragma unroll
            for (int j = 0; j < 4; j++) s_[nt][j] = 0.f;
#pragma unroll
        for (int k8 = 0; k8 < 16; k8++) {
            const int c = k8 * 8 + fc;
            unsigned af[4];
            af[0] = lds32(sb + 4 * (QS_OFF + (r_lo)     * 132 + c));
            af[1] = lds32(sb + 4 * (QS_OFF + (r_lo + 8) * 132 + c));
            af[2] = lds32(sb + 4 * (QS_OFF + (r_lo)     * 132 + c + 4));
            af[3] = lds32(sb + 4 * (QS_OFF + (r_lo + 8) * 132 + c + 4));
#pragma unroll
            for (int nt = 0; nt < 4; nt++) {
                const int n = nt * 8 + fr;
                mma_tf32(s_[nt], af,
                         lds32(sb + 4 * (kO + n * 132 + c)),
                         lds32(sb + 4 * (kO + n * 132 + c + 4)));
            }
        }

        const int k0 = it << 5;
        float mx0 = -3.4e38f, mx1 = -3.4e38f;
#pragma unroll
        for (int nt = 0; nt < 4; nt++) {
            const int col = k0 + nt * 8 + 2 * fc;
            int2 ma = *(const int2*)(adj + (size_t)(q0 + r_lo) * NSEQ + col);
            int2 mb = *(const int2*)(adj + (size_t)(q0 + r_lo + 8) * NSEQ + col);
            s_[nt][0] = ma.x ? s_[nt][0] * rs : -1e9f;
            s_[nt][1] = ma.y ? s_[nt][1] * rs : -1e9f;
            s_[nt][2] = mb.x ? s_[nt][2] * rs : -1e9f;
            s_[nt][3] = mb.y ? s_[nt][3] * rs : -1e9f;
            mx0 = fmaxf(mx0, fmaxf(s_[nt][0], s_[nt][1]));
            mx1 = fmaxf(mx1, fmaxf(s_[nt][2], s_[nt][3]));
        }
        mx0 = fmaxf(mx0, __shfl_xor_sync(~0u, mx0, 1));
        mx0 = fmaxf(mx0, __shfl_xor_sync(~0u, mx0, 2));
        mx1 = fmaxf(mx1, __shfl_xor_sync(~0u, mx1, 1));
        mx1 = fmaxf(mx1, __shfl_xor_sync(~0u, mx1, 2));
        const float mn0 = fmaxf(m0, mx0), mn1 = fmaxf(m1, mx1);
        const float sc0 = __expf(m0 - mn0), sc1 = __expf(m1 - mn1);
        m0 = mn0; m1 = mn1;

        float sum0 = 0.f, sum1 = 0.f;
#pragma unroll
        for (int nt = 0; nt < 4; nt++) {
            s_[nt][0] = __expf(s_[nt][0] - mn0);
            s_[nt][1] = __expf(s_[nt][1] - mn0);
            s_[nt][2] = __expf(s_[nt][2] - mn1);
            s_[nt][3] = __expf(s_[nt][3] - mn1);
            sum0 += s_[nt][0] + s_[nt][1];
            sum1 += s_[nt][2] + s_[nt][3];
            const int pc = nt * 8 + 2 * fc;
            Pw[fr * 36 + pc]           = s_[nt][0];
            Pw[fr * 36 + pc + 1]       = s_[nt][1];
            Pw[(fr + 8) * 36 + pc]     = s_[nt][2];
            Pw[(fr + 8) * 36 + pc + 1] = s_[nt][3];
        }
        sum0 += __shfl_xor_sync(~0u, sum0, 1);
        sum0 += __shfl_xor_sync(~0u, sum0, 2);
        sum1 += __shfl_xor_sync(~0u, sum1, 1);
        sum1 += __shfl_xor_sync(~0u, sum1, 2);
        l0 = l0 * sc0 + sum0;
        l1 = l1 * sc1 + sum1;
        __syncwarp();

#pragma unroll
        for (int nt = 0; nt < 16; nt++) {
            acc_o[nt][0] *= sc0; acc_o[nt][1] *= sc0;
            acc_o[nt][2] *= sc1; acc_o[nt][3] *= sc1;
        }

#pragma unroll
        for (int k8 = 0; k8 < 4; k8++) {
            const int c = k8 * 8 + fc;
            unsigned af[4];
            af[0] = f2tf32(Pw[fr * 36 + c]);
            af[1] = f2tf32(Pw[(fr + 8) * 36 + c]);
            af[2] = f2tf32(Pw[fr * 36 + c + 4]);
            af[3] = f2tf32(Pw[(fr + 8) * 36 + c + 4]);
#pragma unroll
            for (int nt = 0; nt < 16; nt++) {
                const int n = nt * 8 + fr;
                mma_tf32(acc_o[nt], af,
                         lds32(sb + 4 * (vO + c * 136 + n)),
                         lds32(sb + 4 * (vO + (c + 4) * 136 + n)));
            }
        }
        __syncthreads();
    }

    const float inv0 = 1.f / l0, inv1 = 1.f / l1;
    float* Og = g_q + ((size_t)b * NSEQ + q0) * HH + h * DHEAD;
#pragma unroll
    for (int nt = 0; nt < 16; nt++) {
        const int col = nt * 8 + 2 * fc;
        float2 lo = make_float2(rnd32(acc_o[nt][0] * inv0), rnd32(acc_o[nt][1] * inv0));
        float2 hi = make_float2(rnd32(acc_o[nt][2] * inv1), rnd32(acc_o[nt][3] * inv1));
        *(float2*)(Og + (size_t)(r_lo)     * HH + col) = lo;
        *(float2*)(Og + (size_t)(r_lo + 8) * HH + col) = hi;
    }
}

// -------- all-weights transpose, one launch (z = layer*6 + which) --------
__global__ void k_tr_all(const float* __restrict__ Wq, const float* __restrict__ Wk,
                         const float* __restrict__ Wv, const float* __restrict__ Wo,
                         const float* __restrict__ W1, const float* __restrict__ W2,
                         float* __restrict__ pwt) {
    __shared__ float t[32][33];
    const int z = blockIdx.z, j = z / 6, w = z % 6;
    const float* src; float* dst; int R, Cc;
    float* base = pwt + (size_t)j * 3145728;
    switch (w) {
        case 0: src = Wq + (size_t)j * HH * HH;  dst = base;           R = HH;  Cc = HH;  break;
        case 1: src = Wk + (size_t)j * HH * HH;  dst = base + 262144;  R = HH;  Cc = HH;  break;
        case 2: src = Wv + (size_t)j * HH * HH;  dst = base + 524288;  R = HH;  Cc = HH;  break;
        case 3: src = Wo + (size_t)j * HH * HH;  dst = base + 786432;  R = HH;  Cc = HH;  break;
        case 4: src = W1 + (size_t)j * HH * FFD; dst = base + 1048576; R = HH;  Cc = FFD; break;
        default: src = W2 + (size_t)j * FFD * HH; dst = base + 2097152; R = FFD; Cc = HH; break;
    }
    const int c0 = blockIdx.x * 32, r0 = blockIdx.y * 32;
    if (c0 >= Cc || r0 >= R) return;
    const int tx = threadIdx.x, ty = threadIdx.y;
#pragma unroll
    for (int i = 0; i < 4; i++)
        t[ty + 8 * i][tx] = src[(size_t)(r0 + ty + 8 * i) * Cc + c0 + tx];
    __syncthreads();
#pragma unroll
    for (int i = 0; i < 4; i++)
        dst[(size_t)(c0 + ty + 8 * i) * R + r0 + tx] = rnd32(t[tx][ty + 8 * i]);
}

// -------- concat qkv biases --------
__global__ void k_bcat(const float* __restrict__ bq, const float* __restrict__ bk,
                       const float* __restrict__ bv) {
    int i = blockIdx.x * 256 + threadIdx.x;
    if (i >= PP * QKVLD) return;
    int j = i / QKVLD, c = i % QKVLD;
    const float* src = (c < 512) ? bq : ((c < 1024) ? bk : bv);
    g_bcat[i] = src[j * HH + (c & 511)];
}

// -------- build x = concat(vents, renc_w[rels]) (tf32-rounded) --------
__global__ void k_build_x(const float* __restrict__ vents,
                          const float* __restrict__ renc,
                          const int*   __restrict__ rels) {
    int idx = blockIdx.x * blockDim.x + threadIdx.x;
    const int H4 = HH / 4;
    if (idx >= BB * NSEQ * H4) return;
    int hv = idx % H4;
    int n  = (idx / H4) % NSEQ;
    int b  = idx / (H4 * NSEQ);
    float4 val;
    if (n < EE) {
        val = ((const float4*)vents)[(size_t)(b * EE + n) * H4 + hv];
    } else {
        int r = rels[b * RR + (n - EE)];
        val = ((const float4*)renc)[(size_t)r * H4 + hv];
    }
    val.x = rnd32(val.x); val.y = rnd32(val.y);
    val.z = rnd32(val.z); val.w = rnd32(val.w);
    ((float4*)g_x)[idx] = val;
}

// -------- layernorm (optional residual), warp per row --------
__global__ __launch_bounds__(256)
void k_ln(const float* __restrict__ X, const float* __restrict__ Rres,
          const float* __restrict__ g, const float* __restrict__ bsh,
          float* __restrict__ out) {
    const int row  = blockIdx.x * 8 + (threadIdx.x >> 5);
    const int lane = threadIdx.x & 31;
    const float4* xr = (const float4*)(X + (size_t)row * HH);
    float4 v[4];
    float sum = 0.f, sq = 0.f;
#pragma unroll
    for (int i = 0; i < 4; i++) {
        float4 a = xr[lane + 32 * i];
        if (Rres) {
            float4 r = ((const float4*)(Rres + (size_t)row * HH))[lane + 32 * i];
            a.x += r.x; a.y += r.y; a.z += r.z; a.w += r.w;
        }
        v[i] = a;
        sum += a.x + a.y + a.z + a.w;
        sq  += a.x * a.x + a.y * a.y + a.z * a.z + a.w * a.w;
    }
#pragma unroll
    for (int o = 16; o; o >>= 1) {
        sum += __shfl_xor_sync(~0u, sum, o);
        sq  += __shfl_xor_sync(~0u, sq,  o);
    }
    const float mu   = sum * (1.f / HH);
    const float var  = sq * (1.f / HH) - mu * mu;
    const float rstd = rsqrtf(var + 1e-5f);
    float4* op = (float4*)(out + (size_t)row * HH);
#pragma unroll
    for (int i = 0; i < 4; i++) {
        int c4 = lane + 32 * i;
        float4 gg = ((const float4*)g)[c4];
        float4 bb = ((const float4*)bsh)[c4];
        float4 a = v[i];
        a.x = rnd32((a.x - mu) * rstd * gg.x + bb.x);
        a.y = rnd32((a.y - mu) * rstd * gg.y + bb.y);
        a.z = rnd32((a.z - mu) * rstd * gg.z + bb.z);
        a.w = rnd32((a.w - mu) * rstd * gg.w + bb.w);
        op[c4] = a;
    }
}

// -------- output assembly: [glob | gents | emask] --------
__global__ void k_out(float* __restrict__ out) {
    const size_t GENTS = (size_t)BB * NSEQ * HH;
    size_t i = (size_t)blockIdx.x * 256 + threadIdx.x;
    if (i < (size_t)BB * HH) {
        size_t b = i / HH, hc = i % HH;
        out[i] = g_x[b * NSEQ * HH + (size_t)EE * HH + hc];
    }
    if (i < GENTS) out[(size_t)BB * HH + i] = g_x[i];
    if (i < (size_t)BB * NSEQ) out[(size_t)BB * HH + GENTS + i] = 1.0f;
}

extern "C" void kernel_launch(void* const* d_in, const int* in_sizes, int n_in,
                              void* d_out, int out_size) {
    int s = (n_in >= 22) ? 1 : 0;
    const int*   adjs  = (const int*)d_in[0];
    const int*   rels  = (const int*)d_in[1];
    const float* vents = (const float*)d_in[2];
    const float* renc  = (const float*)d_in[3 + s];
    const float* Wq = (const float*)d_in[4 + s];
    const float* Wk = (const float*)d_in[5 + s];
    const float* Wv = (const float*)d_in[6 + s];
    const float* Wo = (const float*)d_in[7 + s];
    const float* W1 = (const float*)d_in[8 + s];
    const float* W2 = (const float*)d_in[9 + s];
    const float* bq = (const float*)d_in[10 + s];
    const float* bk = (const float*)d_in[11 + s];
    const float* bv = (const float*)d_in[12 + s];
    const float* bo = (const float*)d_in[13 + s];
    const float* b1 = (const float*)d_in[14 + s];
    const float* b2 = (const float*)d_in[15 + s];
    const float* ln1g = (const float*)d_in[16 + s];
    const float* ln1b = (const float*)d_in[17 + s];
    const float* ln2g = (const float*)d_in[18 + s];
    const float* ln2b = (const float*)d_in[19 + s];
    const float* pa   = (const float*)d_in[20 + s];

    float *px, *pqkv, *pq, *pk, *pt, *pf, *pwt, *pbc;
    cudaGetSymbolAddress((void**)&px, g_x);
    cudaGetSymbolAddress((void**)&pqkv, g_qkv);
    cudaGetSymbolAddress((void**)&pq, g_q);
    cudaGetSymbolAddress((void**)&pk, g_k);
    cudaGetSymbolAddress((void**)&pt, g_t);
    cudaGetSymbolAddress((void**)&pf, g_f);
    cudaGetSymbolAddress((void**)&pwt, g_wt);
    cudaGetSymbolAddress((void**)&pbc, g_bcat);

    cudaFuncSetAttribute(k_mm<0>, cudaFuncAttributeMaxDynamicSharedMemorySize, SMEM_DYN);
    cudaFuncSetAttribute(k_mm<1>, cudaFuncAttributeMaxDynamicSharedMemorySize, SMEM_DYN);
    cudaFuncSetAttribute(k_mm<2>, cudaFuncAttributeMaxDynamicSharedMemorySize, SMEM_DYN);
    cudaFuncSetAttribute(k_flash, cudaFuncAttributeMaxDynamicSharedMemorySize, FLASH_SMEM);

    k_build_x<<<(BB * NSEQ * (HH / 4) + 255) / 256, 256>>>(vents, renc, rels);
    k_tr_all<<<dim3(64, 64, 12), dim3(32, 8)>>>(Wq, Wk, Wv, Wo, W1, W2, pwt);
    k_bcat<<<(PP * QKVLD + 255) / 256, 256>>>(bq, bk, bv);

    const size_t LSTR = 3145728;
    for (int j = 0; j < PP; j++) {
        float* base = pwt + j * LSTR;
        // fused QKV: C[8192,1536] = x @ [Wq|Wk|Wv]^T
        k_mm<1><<<dim3(QKVLD / 128, MTOK / 128), 256, SMEM_DYN>>>(
            px, HH, base, HH, pqkv, QKVLD, HH, pbc + j * QKVLD, nullptr);

        k_flash<<<dim3(NSEQ / 64, BB * NHEAD), 128, FLASH_SMEM>>>(adjs);   // attn out -> g_q

        k_mm<1><<<dim3(HH / 128, MTOK / 128), 256, SMEM_DYN>>>(
            pq, HH, base + 786432, HH, pk, HH, HH, bo + j * HH, nullptr);
        k_ln<<<MTOK / 8, 256>>>(pk, nullptr, ln1g + j * HH, ln1b + j * HH, pt);

        k_mm<2><<<dim3(FFD / 128, MTOK / 128), 256, SMEM_DYN>>>(
            pt, HH, base + 1048576, HH, pf, FFD, HH, b1 + j * FFD, pa + j * FFD);
        k_mm<1><<<dim3(HH / 128, MTOK / 128), 256, SMEM_DYN>>>(
            pf, FFD, base + 2097152, FFD, pk, HH, FFD, b2 + j * HH, nullptr);

        k_ln<<<MTOK / 8, 256>>>(pk, pt, ln2g + j * HH, ln2b + j * HH, px);
    }

    k_out<<<(BB * NSEQ * HH + 255) / 256, 256>>>((float*)d_out);
}

// round 14
// speedup vs baseline: 1.0205x; 1.0205x over previous
#include <cuda_runtime.h>
#include <cstdint>

// Problem constants
#define BB     4
#define NSEQ   2048
#define EE     1600
#define RR     448
#define HH     512
#define NHEAD  4
#define DHEAD  128
#define PP     2
#define FFD    2048
#define MTOK   (BB*NSEQ)
#define QKVLD  1536

// -------- scratch (device globals; no allocation allowed) --------
__device__ float g_x[(size_t)BB*NSEQ*HH];
__device__ float g_qkv[(size_t)BB*NSEQ*QKVLD];
__device__ float g_q[(size_t)BB*NSEQ*HH];
__device__ float g_k[(size_t)BB*NSEQ*HH];
__device__ float g_t[(size_t)BB*NSEQ*HH];
__device__ float g_f[(size_t)BB*NSEQ*FFD];
__device__ float g_wt[(size_t)PP*3145728];            // transposed weights
__device__ float g_bcat[PP*QKVLD];                    // concat qkv bias

// ---------------- helpers ----------------
__device__ __forceinline__ unsigned f2tf32(float x) {
    unsigned r; asm("cvt.rna.tf32.f32 %0, %1;" : "=r"(r) : "f"(x)); return r;
}
__device__ __forceinline__ float rnd32(float x) {
    return __uint_as_float(f2tf32(x));
}
__device__ __forceinline__ uint32_t smem_u32(const void* p) {
    uint32_t a;
    asm("{ .reg .u64 t; cvta.to.shared.u64 t, %1; cvt.u32.u64 %0, t; }" : "=r"(a) : "l"(p));
    return a;
}
__device__ __forceinline__ unsigned lds32(uint32_t a) {
    unsigned v; asm("ld.shared.b32 %0, [%1];" : "=r"(v) : "r"(a)); return v;
}
// ldmatrix x4: four 8x8 b16 tiles -> 4 regs/lane (tf32 fragment gather)
__device__ __forceinline__ void ldsm4(unsigned* r, uint32_t a) {
    asm volatile("ldmatrix.sync.aligned.m8n8.x4.shared.b16 {%0,%1,%2,%3}, [%4];"
                 : "=r"(r[0]), "=r"(r[1]), "=r"(r[2]), "=r"(r[3]) : "r"(a));
}
#define SWZ128(o) ((o) ^ (((o) >> 3) & 0x70))

__device__ __forceinline__ void mma_tf32(float* d, const unsigned* a,
                                         unsigned b0, unsigned b1) {
    asm volatile("mma.sync.aligned.m16n8k8.row.col.f32.tf32.tf32.f32 "
                 "{%0,%1,%2,%3}, {%4,%5,%6,%7}, {%8,%9}, {%0,%1,%2,%3};"
                 : "+f"(d[0]), "+f"(d[1]), "+f"(d[2]), "+f"(d[3])
                 : "r"(a[0]), "r"(a[1]), "r"(a[2]), "r"(a[3]),
                   "r"(b0), "r"(b1));
}

#define CP16(d, s)   asm volatile("cp.async.cg.shared.global [%0], [%1], 16;" :: "r"(d), "l"(s))
#define CP_COMMIT()  asm volatile("cp.async.commit_group;")
#define CP_WAIT(n)   asm volatile("cp.async.wait_group %0;" :: "n"(n))

#define STAGE_SZ   32768     // GEMM: A(16KB, 128x32 f32 SW128) + B(16KB)
#define NSTAGE     3
#define SMEM_DYN   (NSTAGE*STAGE_SZ)

// ======== pipelined tf32 mma.sync GEMM, 128x128 tile + ldmatrix ========
// 256 threads, warp grid 2(m) x 4(n), warp tile 64x32, BK=32.
// __launch_bounds__(256,2): <=128 regs -> 2 CTAs/SM. 3-stage cp.async pipeline.
template<int EPI>   // 0 none, 1 +bias, 2 +bias+prelu
__global__ __launch_bounds__(256, 2)
void k_mm(const float* __restrict__ A, int lda,
          const float* __restrict__ B, int ldb,
          float* __restrict__ C, int ldc, int K,
          const float* __restrict__ bias,
          const float* __restrict__ alpha)
{
    extern __shared__ __align__(1024) char dynsmem[];
    const uint32_t sb = smem_u32(dynsmem);
    const int tid = threadIdx.x, lane = tid & 31, wid = tid >> 5;
    const int wm = wid & 1, wn = wid >> 1;
    const int row0 = blockIdx.y * 128, col0 = blockIdx.x * 128;

    auto copy_tile = [&](int it, int s) {
        const uint32_t a_s = sb + s * STAGE_SZ;
        const uint32_t b_s = a_s + 16384;
        const int k0 = it << 5;
#pragma unroll
        for (int u = 0; u < 4; u++) {
            int idx = tid + 256 * u;
            int r = idx >> 3, c16 = (idx & 7) << 4;
            uint32_t sw = SWZ128((r << 7) + c16);
            CP16(a_s + sw, A + (size_t)(row0 + r) * lda + k0 + (c16 >> 2));
            CP16(b_s + sw, B + (size_t)(col0 + r) * ldb + k0 + (c16 >> 2));
        }
    };

    float acc[4][4][4];
#pragma unroll
    for (int t = 0; t < 4; t++)
#pragma unroll
        for (int nt = 0; nt < 4; nt++)
#pragma unroll
            for (int r = 0; r < 4; r++) acc[t][nt][r] = 0.f;

    const int T = K >> 5;
    copy_tile(0, 0);
    CP_COMMIT();
    if (T > 1) { copy_tile(1, 1); CP_COMMIT(); }

    // ldmatrix lane addressing: lanes 0-15 -> rows (lane&15), tf32 cols +0..3;
    // lanes 16-31 -> same rows, cols +4..7.
    const int li = lane & 15;
    const int chb = ((lane >> 4) << 4);       // byte offset of col-half

    int s = 0, sn = 2;                         // current stage, next-fill stage
    for (int it = 0; it < T; it++) {
        if (it + 2 < T) {
            copy_tile(it + 2, sn);
            CP_COMMIT();
            CP_WAIT(2);
        } else if (it + 1 < T) {
            CP_WAIT(1);
        } else {
            CP_WAIT(0);
        }
        __syncthreads();

        const uint32_t a_s = sb + s * STAGE_SZ;
        const uint32_t b_s = a_s + 16384;
        const uint32_t aR0 = a_s + ((wm * 64 + li) << 7);
        const uint32_t bR0 = b_s + ((wn * 32 + li) << 7);
#pragma unroll
        for (int k8 = 0; k8 < 4; k8++) {
            const uint32_t cb = (k8 << 5) + chb;   // byte col offset
            unsigned af[4][4], bt[2][4];
#pragma unroll
            for (int t = 0; t < 4; t++)
                ldsm4(af[t], SWZ128((aR0 + (t << 11)) + cb));
#pragma unroll
            for (int p = 0; p < 2; p++)
                ldsm4(bt[p], SWZ128((bR0 + (p << 11)) + cb));
#pragma unroll
            for (int t = 0; t < 4; t++) {
                mma_tf32(acc[t][0], af[t], bt[0][0], bt[0][2]);
                mma_tf32(acc[t][1], af[t], bt[0][1], bt[0][3]);
                mma_tf32(acc[t][2], af[t], bt[1][0], bt[1][2]);
                mma_tf32(acc[t][3], af[t], bt[1][1], bt[1][3]);
            }
        }
        __syncthreads();
        s = (s == NSTAGE - 1) ? 0 : s + 1;
        sn = (sn == NSTAGE - 1) ? 0 : sn + 1;
    }

    const int r = lane >> 2;
    const int cq = (lane & 3) << 1;
#pragma unroll
    for (int t = 0; t < 4; t++) {
        const int row = row0 + wm * 64 + t * 16 + r;
#pragma unroll
        for (int nt = 0; nt < 4; nt++) {
            const int col = col0 + wn * 32 + nt * 8 + cq;
            float2 v0 = make_float2(acc[t][nt][0], acc[t][nt][1]);
            float2 v1 = make_float2(acc[t][nt][2], acc[t][nt][3]);
            if (EPI == 1 || EPI == 2) {
                float b0 = bias[col], b1 = bias[col + 1];
                v0.x += b0; v0.y += b1; v1.x += b0; v1.y += b1;
            }
            if (EPI == 2) {
                float a0 = alpha[col], a1 = alpha[col + 1];
                v0.x = (v0.x >= 0.f) ? v0.x : a0 * v0.x;
                v0.y = (v0.y >= 0.f) ? v0.y : a1 * v0.y;
                v1.x = (v1.x >= 0.f) ? v1.x : a0 * v1.x;
                v1.y = (v1.y >= 0.f) ? v1.y : a1 * v1.y;
            }
            v0.x = rnd32(v0.x); v0.y = rnd32(v0.y);
            v1.x = rnd32(v1.x); v1.y = rnd32(v1.y);
            *(float2*)(C + (size_t)row * ldc + col)       = v0;
            *(float2*)(C + (size_t)(row + 8) * ldc + col) = v1;
        }
    }
}

// ======== fused flash attention (validated; QKV from g_qkv) ========
#define QS_OFF  0u
#define KS_OFF  8448u
#define KS_LEN  4224u
#define VS_OFF  16896u
#define VS_LEN  4352u
#define PS_OFF  25600u
#define FLASH_SMEM  111616   // bytes -> 2 CTAs/SM

__global__ __launch_bounds__(128)
void k_flash(const int* __restrict__ adjs) {
    extern __shared__ __align__(16) char dynsmem[];
    float* smemf = (float*)dynsmem;
    const uint32_t sb = smem_u32(dynsmem);
    const int tid = threadIdx.x, lane = tid & 31, wid = tid >> 5;
    const int fr = lane >> 2, fc = lane & 3;
    const int z = blockIdx.y, b = z >> 2, h = z & 3;
    const int q0 = blockIdx.x * 64;
    const float* Qg = g_qkv + ((size_t)b * NSEQ + q0) * QKVLD + h * DHEAD;
    const float* Kg = g_qkv + (size_t)b * NSEQ * QKVLD + 512 + h * DHEAD;
    const float* Vg = g_qkv + (size_t)b * NSEQ * QKVLD + 1024 + h * DHEAD;
    const int* adj = adjs + (size_t)b * NSEQ * NSEQ;
    const int r_lo = wid * 16 + fr;
    float* Pw = smemf + PS_OFF + wid * 576;   // [16][36] per warp

#pragma unroll
    for (int u = 0; u < 16; u++) {
        int idx = tid + 128 * u;
        int r = idx >> 5, cg = idx & 31;
        float4 v = *(const float4*)(Qg + (size_t)r * QKVLD + 4 * cg);
        *(float4*)(smemf + QS_OFF + r * 132 + 4 * cg) = v;
    }

    auto stage_kv = [&](int it, int s) {
        const int k0 = it << 5;
        const uint32_t kO = KS_OFF + s * KS_LEN;
        const uint32_t vO = VS_OFF + s * VS_LEN;
#pragma unroll
        for (int u = 0; u < 8; u++) {
            int idx = tid + 128 * u;
            int r = idx >> 5, cg = idx & 31;
            CP16(sb + 4 * (kO + r * 132 + 4 * cg), Kg + (size_t)(k0 + r) * QKVLD + 4 * cg);
            CP16(sb + 4 * (vO + r * 136 + 4 * cg), Vg + (size_t)(k0 + r) * QKVLD + 4 * cg);
        }
    };

    float acc_o[16][4];
#pragma unroll
    for (int nt = 0; nt < 16; nt++)
#pragma unroll
        for (int j = 0; j < 4; j++) acc_o[nt][j] = 0.f;
    float m0 = -3.4e38f, m1 = -3.4e38f, l0 = 0.f, l1 = 0.f;
    const float rs = 0.08838834764831845f;

    const int T = NSEQ / 32;
    stage_kv(0, 0);
    CP_COMMIT();

    for (int it = 0; it < T; it++) {
        const int s = it & 1;
        if (it + 1 < T) {
            stage_kv(it + 1, s ^ 1);
            CP_COMMIT();
            CP_WAIT(1);
        } else {
            CP_WAIT(0);
        }
        __syncthreads();
        const uint32_t kO = KS_OFF + s * KS_LEN;
        const uint32_t vO = VS_OFF + s * VS_LEN;

        float s_[4][4];
#pragma unroll
        for (int nt = 0; nt < 4; nt++)
#pragma unroll
            for (int j = 0; j < 4; j++) s_[nt][j] = 0.f;
#pragma unroll
        for (int k8 = 0; k8 < 16; k8++) {
            const int c = k8 * 8 + fc;
            unsigned af[4];
            af[0] = lds32(sb + 4 * (QS_OFF + (r_lo)     * 132 + c));
            af[1] = lds32(sb + 4 * (QS_OFF + (r_lo + 8) * 132 + c));
            af[2] = lds32(sb + 4 * (QS_OFF + (r_lo)     * 132 + c + 4));
            af[3] = lds32(sb + 4 * (QS_OFF + (r_lo + 8) * 132 + c + 4));
#pragma unroll
            for (int nt = 0; nt < 4; nt++) {
                const int n = nt * 8 + fr;
                mma_tf32(s_[nt], af,
                         lds32(sb + 4 * (kO + n * 132 + c)),
                         lds32(sb + 4 * (kO + n * 132 + c + 4)));
            }
        }

        const int k0 = it << 5;
        float mx0 = -3.4e38f, mx1 = -3.4e38f;
#pragma unroll
        for (int nt = 0; nt < 4; nt++) {
            const int col = k0 + nt * 8 + 2 * fc;
            int2 ma = *(const int2*)(adj + (size_t)(q0 + r_lo) * NSEQ + col);
            int2 mb = *(const int2*)(adj + (size_t)(q0 + r_lo + 8) * NSEQ + col);
            s_[nt][0] = ma.x ? s_[nt][0] * rs : -1e9f;
            s_[nt][1] = ma.y ? s_[nt][1] * rs : -1e9f;
            s_[nt][2] = mb.x ? s_[nt][2] * rs : -1e9f;
            s_[nt][3] = mb.y ? s_[nt][3] * rs : -1e9f;
            mx0 = fmaxf(mx0, fmaxf(s_[nt][0], s_[nt][1]));
            mx1 = fmaxf(mx1, fmaxf(s_[nt][2], s_[nt][3]));
        }
        mx0 = fmaxf(mx0, __shfl_xor_sync(~0u, mx0, 1));
        mx0 = fmaxf(mx0, __shfl_xor_sync(~0u, mx0, 2));
        mx1 = fmaxf(mx1, __shfl_xor_sync(~0u, mx1, 1));
        mx1 = fmaxf(mx1, __shfl_xor_sync(~0u, mx1, 2));
        const float mn0 = fmaxf(m0, mx0), mn1 = fmaxf(m1, mx1);
        const float sc0 = __expf(m0 - mn0), sc1 = __expf(m1 - mn1);
        m0 = mn0; m1 = mn1;

        float sum0 = 0.f, sum1 = 0.f;
#pragma unroll
        for (int nt = 0; nt < 4; nt++) {
            s_[nt][0] = __expf(s_[nt][0] - mn0);
            s_[nt][1] = __expf(s_[nt][1] - mn0);
            s_[nt][2] = __expf(s_[nt][2] - mn1);
            s_[nt][3] = __expf(s_[nt][3] - mn1);
            sum0 += s_[nt][0] + s_[nt][1];
            sum1 += s_[nt][2] + s_[nt][3];
            const int pc = nt * 8 + 2 * fc;
            Pw[fr * 36 + pc]           = s_[nt][0];
            Pw[fr * 36 + pc + 1]       = s_[nt][1];
            Pw[(fr + 8) * 36 + pc]     = s_[nt][2];
            Pw[(fr + 8) * 36 + pc + 1] = s_[nt][3];
        }
        sum0 += __shfl_xor_sync(~0u, sum0, 1);
        sum0 += __shfl_xor_sync(~0u, sum0, 2);
        sum1 += __shfl_xor_sync(~0u, sum1, 1);
        sum1 += __shfl_xor_sync(~0u, sum1, 2);
        l0 = l0 * sc0 + sum0;
        l1 = l1 * sc1 + sum1;
        __syncwarp();

#pragma unroll
        for (int nt = 0; nt < 16; nt++) {
            acc_o[nt][0] *= sc0; acc_o[nt][1] *= sc0;
            acc_o[nt][2] *= sc1; acc_o[nt][3] *= sc1;
        }

#pragma unroll
        for (int k8 = 0; k8 < 4; k8++) {
            const int c = k8 * 8 + fc;
            unsigned af[4];
            af[0] = f2tf32(Pw[fr * 36 + c]);
            af[1] = f2tf32(Pw[(fr + 8) * 36 + c]);
            af[2] = f2tf32(Pw[fr * 36 + c + 4]);
            af[3] = f2tf32(Pw[(fr + 8) * 36 + c + 4]);
#pragma unroll
            for (int nt = 0; nt < 16; nt++) {
                const int n = nt * 8 + fr;
                mma_tf32(acc_o[nt], af,
                         lds32(sb + 4 * (vO + c * 136 + n)),
                         lds32(sb + 4 * (vO + (c + 4) * 136 + n)));
            }
        }
        __syncthreads();
    }

    const float inv0 = 1.f / l0, inv1 = 1.f / l1;
    float* Og = g_q + ((size_t)b * NSEQ + q0) * HH + h * DHEAD;
#pragma unroll
    for (int nt = 0; nt < 16; nt++) {
        const int col = nt * 8 + 2 * fc;
        float2 lo = make_float2(rnd32(acc_o[nt][0] * inv0), rnd32(acc_o[nt][1] * inv0));
        float2 hi = make_float2(rnd32(acc_o[nt][2] * inv1), rnd32(acc_o[nt][3] * inv1));
        *(float2*)(Og + (size_t)(r_lo)     * HH + col) = lo;
        *(float2*)(Og + (size_t)(r_lo + 8) * HH + col) = hi;
    }
}

// -------- all-weights transpose, one launch (z = layer*6 + which) --------
__global__ void k_tr_all(const float* __restrict__ Wq, const float* __restrict__ Wk,
                         const float* __restrict__ Wv, const float* __restrict__ Wo,
                         const float* __restrict__ W1, const float* __restrict__ W2,
                         float* __restrict__ pwt) {
    __shared__ float t[32][33];
    const int z = blockIdx.z, j = z / 6, w = z % 6;
    const float* src; float* dst; int R, Cc;
    float* base = pwt + (size_t)j * 3145728;
    switch (w) {
        case 0: src = Wq + (size_t)j * HH * HH;  dst = base;           R = HH;  Cc = HH;  break;
        case 1: src = Wk + (size_t)j * HH * HH;  dst = base + 262144;  R = HH;  Cc = HH;  break;
        case 2: src = Wv + (size_t)j * HH * HH;  dst = base + 524288;  R = HH;  Cc = HH;  break;
        case 3: src = Wo + (size_t)j * HH * HH;  dst = base + 786432;  R = HH;  Cc = HH;  break;
        case 4: src = W1 + (size_t)j * HH * FFD; dst = base + 1048576; R = HH;  Cc = FFD; break;
        default: src = W2 + (size_t)j * FFD * HH; dst = base + 2097152; R = FFD; Cc = HH; break;
    }
    const int c0 = blockIdx.x * 32, r0 = blockIdx.y * 32;
    if (c0 >= Cc || r0 >= R) return;
    const int tx = threadIdx.x, ty = threadIdx.y;
#pragma unroll
    for (int i = 0; i < 4; i++)
        t[ty + 8 * i][tx] = src[(size_t)(r0 + ty + 8 * i) * Cc + c0 + tx];
    __syncthreads();
#pragma unroll
    for (int i = 0; i < 4; i++)
        dst[(size_t)(c0 + ty + 8 * i) * R + r0 + tx] = rnd32(t[tx][ty + 8 * i]);
}

// -------- concat qkv biases --------
__global__ void k_bcat(const float* __restrict__ bq, const float* __restrict__ bk,
                       const float* __restrict__ bv) {
    int i = blockIdx.x * 256 + threadIdx.x;
    if (i >= PP * QKVLD) return;
    int j = i / QKVLD, c = i % QKVLD;
    const float* src = (c < 512) ? bq : ((c < 1024) ? bk : bv);
    g_bcat[i] = src[j * HH + (c & 511)];
}

// -------- build x = concat(vents, renc_w[rels]) (tf32-rounded) --------
__global__ void k_build_x(const float* __restrict__ vents,
                          const float* __restrict__ renc,
                          const int*   __restrict__ rels) {
    int idx = blockIdx.x * blockDim.x + threadIdx.x;
    const int H4 = HH / 4;
    if (idx >= BB * NSEQ * H4) return;
    int hv = idx % H4;
    int n  = (idx / H4) % NSEQ;
    int b  = idx / (H4 * NSEQ);
    float4 val;
    if (n < EE) {
        val = ((const float4*)vents)[(size_t)(b * EE + n) * H4 + hv];
    } else {
        int r = rels[b * RR + (n - EE)];
        val = ((const float4*)renc)[(size_t)r * H4 + hv];
    }
    val.x = rnd32(val.x); val.y = rnd32(val.y);
    val.z = rnd32(val.z); val.w = rnd32(val.w);
    ((float4*)g_x)[idx] = val;
}

// -------- layernorm (optional residual), warp per row --------
__global__ __launch_bounds__(256)
void k_ln(const float* __restrict__ X, const float* __restrict__ Rres,
          const float* __restrict__ g, const float* __restrict__ bsh,
          float* __restrict__ out) {
    const int row  = blockIdx.x * 8 + (threadIdx.x >> 5);
    const int lane = threadIdx.x & 31;
    const float4* xr = (const float4*)(X + (size_t)row * HH);
    float4 v[4];
    float sum = 0.f, sq = 0.f;
#pragma unroll
    for (int i = 0; i < 4; i++) {
        float4 a = xr[lane + 32 * i];
        if (Rres) {
            float4 r = ((const float4*)(Rres + (size_t)row * HH))[lane + 32 * i];
            a.x += r.x; a.y += r.y; a.z += r.z; a.w += r.w;
        }
        v[i] = a;
        sum += a.x + a.y + a.z + a.w;
        sq  += a.x * a.x + a.y * a.y + a.z * a.z + a.w * a.w;
    }
#pragma unroll
    for (int o = 16; o; o >>= 1) {
        sum += __shfl_xor_sync(~0u, sum, o);
        sq  += __shfl_xor_sync(~0u, sq,  o);
    }
    const float mu   = sum * (1.f / HH);
    const float var  = sq * (1.f / HH) - mu * mu;
    const float rstd = rsqrtf(var + 1e-5f);
    float4* op = (float4*)(out + (size_t)row * HH);
#pragma unroll
    for (int i = 0; i < 4; i++) {
        int c4 = lane + 32 * i;
        float4 gg = ((const float4*)g)[c4];
        float4 bb = ((const float4*)bsh)[c4];
        float4 a = v[i];
        a.x = rnd32((a.x - mu) * rstd * gg.x + bb.x);
        a.y = rnd32((a.y - mu) * rstd * gg.y + bb.y);
        a.z = rnd32((a.z - mu) * rstd * gg.z + bb.z);
        a.w = rnd32((a.w - mu) * rstd * gg.w + bb.w);
        op[c4] = a;
    }
}

// -------- output assembly: [glob | gents | emask] --------
__global__ void k_out(float* __restrict__ out) {
    const size_t GENTS = (size_t)BB * NSEQ * HH;
    size_t i = (size_t)blockIdx.x * 256 + threadIdx.x;
    if (i < (size_t)BB * HH) {
        size_t b = i / HH, hc = i % HH;
        out[i] = g_x[b * NSEQ * HH + (size_t)EE * HH + hc];
    }
    if (i < GENTS) out[(size_t)BB * HH + i] = g_x[i];
    if (i < (size_t)BB * NSEQ) out[(size_t)BB * HH + GENTS + i] = 1.0f;
}

extern "C" void kernel_launch(void* const* d_in, const int* in_sizes, int n_in,
                              void* d_out, int out_size) {
    int s = (n_in >= 22) ? 1 : 0;
    const int*   adjs  = (const int*)d_in[0];
    const int*   rels  = (const int*)d_in[1];
    const float* vents = (const float*)d_in[2];
    const float* renc  = (const float*)d_in[3 + s];
    const float* Wq = (const float*)d_in[4 + s];
    const float* Wk = (const float*)d_in[5 + s];
    const float* Wv = (const float*)d_in[6 + s];
    const float* Wo = (const float*)d_in[7 + s];
    const float* W1 = (const float*)d_in[8 + s];
    const float* W2 = (const float*)d_in[9 + s];
    const float* bq = (const float*)d_in[10 + s];
    const float* bk = (const float*)d_in[11 + s];
    const float* bv = (const float*)d_in[12 + s];
    const float* bo = (const float*)d_in[13 + s];
    const float* b1 = (const float*)d_in[14 + s];
    const float* b2 = (const float*)d_in[15 + s];
    const float* ln1g = (const float*)d_in[16 + s];
    const float* ln1b = (const float*)d_in[17 + s];
    const float* ln2g = (const float*)d_in[18 + s];
    const float* ln2b = (const float*)d_in[19 + s];
    const float* pa   = (const float*)d_in[20 + s];

    float *px, *pqkv, *pq, *pk, *pt, *pf, *pwt, *pbc;
    cudaGetSymbolAddress((void**)&px, g_x);
    cudaGetSymbolAddress((void**)&pqkv, g_qkv);
    cudaGetSymbolAddress((void**)&pq, g_q);
    cudaGetSymbolAddress((void**)&pk, g_k);
    cudaGetSymbolAddress((void**)&pt, g_t);
    cudaGetSymbolAddress((void**)&pf, g_f);
    cudaGetSymbolAddress((void**)&pwt, g_wt);
    cudaGetSymbolAddress((void**)&pbc, g_bcat);

    cudaFuncSetAttribute(k_mm<0>, cudaFuncAttributeMaxDynamicSharedMemorySize, SMEM_DYN);
    cudaFuncSetAttribute(k_mm<1>, cudaFuncAttributeMaxDynamicSharedMemorySize, SMEM_DYN);
    cudaFuncSetAttribute(k_mm<2>, cudaFuncAttributeMaxDynamicSharedMemorySize, SMEM_DYN);
    cudaFuncSetAttribute(k_flash, cudaFuncAttributeMaxDynamicSharedMemorySize, FLASH_SMEM);

    k_build_x<<<(BB * NSEQ * (HH / 4) + 255) / 256, 256>>>(vents, renc, rels);
    k_tr_all<<<dim3(64, 64, 12), dim3(32, 8)>>>(Wq, Wk, Wv, Wo, W1, W2, pwt);
    k_bcat<<<(PP * QKVLD + 255) / 256, 256>>>(bq, bk, bv);

    const size_t LSTR = 3145728;
    for (int j = 0; j < PP; j++) {
        float* base = pwt + j * LSTR;
        // fused QKV: C[8192,1536] = x @ [Wq|Wk|Wv]^T
        k_mm<1><<<dim3(QKVLD / 128, MTOK / 128), 256, SMEM_DYN>>>(
            px, HH, base, HH, pqkv, QKVLD, HH, pbc + j * QKVLD, nullptr);

        k_flash<<<dim3(NSEQ / 64, BB * NHEAD), 128, FLASH_SMEM>>>(adjs);   // attn out -> g_q

        k_mm<1><<<dim3(HH / 128, MTOK / 128), 256, SMEM_DYN>>>(
            pq, HH, base + 786432, HH, pk, HH, HH, bo + j * HH, nullptr);
        k_ln<<<MTOK / 8, 256>>>(pk, nullptr, ln1g + j * HH, ln1b + j * HH, pt);

        k_mm<2><<<dim3(FFD / 128, MTOK / 128), 256, SMEM_DYN>>>(
            pt, HH, base + 1048576, HH, pf, FFD, HH, b1 + j * FFD, pa + j * FFD);
        k_mm<1><<<dim3(HH / 128, MTOK / 128), 256, SMEM_DYN>>>(
            pf, FFD, base + 2097152, FFD, pk, HH, FFD, b2 + j * HH, nullptr);

        k_ln<<<MTOK / 8, 256>>>(pk, pt, ln2g + j * HH, ln2b + j * HH, px);
    }

    k_out<<<(BB * NSEQ * HH + 255) / 256, 256>>>((float*)d_out);
}

// round 15
// speedup vs baseline: 1.1015x; 1.0793x over previous
#include <cuda_runtime.h>
#include <cstdint>

// Problem constants
#define BB     4
#define NSEQ   2048
#define EE     1600
#define RR     448
#define HH     512
#define NHEAD  4
#define DHEAD  128
#define PP     2
#define FFD    2048
#define MTOK   (BB*NSEQ)
#define QKVLD  1536

// -------- scratch (device globals; no allocation allowed) --------
__device__ float g_x[(size_t)BB*NSEQ*HH];
__device__ float g_qkv[(size_t)BB*NSEQ*QKVLD];
__device__ float g_q[(size_t)BB*NSEQ*HH];
__device__ float g_k[(size_t)BB*NSEQ*HH];
__device__ float g_t[(size_t)BB*NSEQ*HH];
__device__ float g_f[(size_t)BB*NSEQ*FFD];
__device__ float g_wt[(size_t)PP*3145728];            // transposed weights
__device__ float g_bcat[PP*QKVLD];                    // concat qkv bias

// ---------------- helpers ----------------
__device__ __forceinline__ unsigned f2tf32(float x) {
    unsigned r; asm("cvt.rna.tf32.f32 %0, %1;" : "=r"(r) : "f"(x)); return r;
}
__device__ __forceinline__ float rnd32(float x) {
    return __uint_as_float(f2tf32(x));
}
__device__ __forceinline__ uint32_t smem_u32(const void* p) {
    uint32_t a;
    asm("{ .reg .u64 t; cvta.to.shared.u64 t, %1; cvt.u32.u64 %0, t; }" : "=r"(a) : "l"(p));
    return a;
}
__device__ __forceinline__ unsigned lds32(uint32_t a) {
    unsigned v; asm("ld.shared.b32 %0, [%1];" : "=r"(v) : "r"(a)); return v;
}
// ldmatrix x4: four 8x8 b16 tiles -> 4 regs/lane (tf32 fragment gather)
__device__ __forceinline__ void ldsm4(unsigned* r, uint32_t a) {
    asm volatile("ldmatrix.sync.aligned.m8n8.x4.shared.b16 {%0,%1,%2,%3}, [%4];"
                 : "=r"(r[0]), "=r"(r[1]), "=r"(r[2]), "=r"(r[3]) : "r"(a));
}
#define SWZ128(o) ((o) ^ (((o) >> 3) & 0x70))

__device__ __forceinline__ void mma_tf32(float* d, const unsigned* a,
                                         unsigned b0, unsigned b1) {
    asm volatile("mma.sync.aligned.m16n8k8.row.col.f32.tf32.tf32.f32 "
                 "{%0,%1,%2,%3}, {%4,%5,%6,%7}, {%8,%9}, {%0,%1,%2,%3};"
                 : "+f"(d[0]), "+f"(d[1]), "+f"(d[2]), "+f"(d[3])
                 : "r"(a[0]), "r"(a[1]), "r"(a[2]), "r"(a[3]),
                   "r"(b0), "r"(b1));
}

#define CP16(d, s)   asm volatile("cp.async.cg.shared.global [%0], [%1], 16;" :: "r"(d), "l"(s))
#define CP_COMMIT()  asm volatile("cp.async.commit_group;")
#define CP_WAIT(n)   asm volatile("cp.async.wait_group %0;" :: "n"(n))

#define STAGE_SZ   32768     // GEMM: A(16KB, 128x32 f32 SW128) + B(16KB)
#define SMEM_DYN   (2*STAGE_SZ)

// ======== pipelined tf32 mma.sync GEMM (EXACT R12 version — frozen) ========
// 256 threads, warp grid 2(m) x 4(n), warp tile 64x32, BK=32, 2-stage.
// __launch_bounds__(256,2): <=128 regs -> 2 CTAs/SM.
template<int EPI>   // 0 none, 1 +bias, 2 +bias+prelu
__global__ __launch_bounds__(256, 2)
void k_mm(const float* __restrict__ A, int lda,
          const float* __restrict__ B, int ldb,
          float* __restrict__ C, int ldc, int K,
          const float* __restrict__ bias,
          const float* __restrict__ alpha)
{
    extern __shared__ __align__(1024) char dynsmem[];
    const uint32_t sb = smem_u32(dynsmem);
    const int tid = threadIdx.x, lane = tid & 31, wid = tid >> 5;
    const int wm = wid & 1, wn = wid >> 1;
    const int row0 = blockIdx.y * 128, col0 = blockIdx.x * 128;

    auto copy_tile = [&](int it, int s) {
        const uint32_t a_s = sb + s * STAGE_SZ;
        const uint32_t b_s = a_s + 16384;
        const int k0 = it << 5;
#pragma unroll
        for (int u = 0; u < 4; u++) {
            int idx = tid + 256 * u;
            int r = idx >> 3, c16 = (idx & 7) << 4;
            uint32_t sw = SWZ128((r << 7) + c16);
            CP16(a_s + sw, A + (size_t)(row0 + r) * lda + k0 + (c16 >> 2));
            CP16(b_s + sw, B + (size_t)(col0 + r) * ldb + k0 + (c16 >> 2));
        }
    };

    float acc[4][4][4];
#pragma unroll
    for (int t = 0; t < 4; t++)
#pragma unroll
        for (int nt = 0; nt < 4; nt++)
#pragma unroll
            for (int r = 0; r < 4; r++) acc[t][nt][r] = 0.f;

    const int T = K >> 5;
    copy_tile(0, 0);
    CP_COMMIT();

    const int li = lane & 15;
    const int chb = ((lane >> 4) << 4);       // byte offset of col-half

    for (int it = 0; it < T; it++) {
        const int s = it & 1;
        if (it + 1 < T) {
            copy_tile(it + 1, s ^ 1);
            CP_COMMIT();
            CP_WAIT(1);
        } else {
            CP_WAIT(0);
        }
        __syncthreads();

        const uint32_t a_s = sb + s * STAGE_SZ;
        const uint32_t b_s = a_s + 16384;
        const uint32_t aR0 = a_s + ((wm * 64 + li) << 7);
        const uint32_t bR0 = b_s + ((wn * 32 + li) << 7);
#pragma unroll
        for (int k8 = 0; k8 < 4; k8++) {
            const uint32_t cb = (k8 << 5) + chb;   // byte col offset
            unsigned af[4][4], bt[2][4];
#pragma unroll
            for (int t = 0; t < 4; t++)
                ldsm4(af[t], SWZ128((aR0 + (t << 11)) + cb));
#pragma unroll
            for (int p = 0; p < 2; p++)
                ldsm4(bt[p], SWZ128((bR0 + (p << 11)) + cb));
#pragma unroll
            for (int t = 0; t < 4; t++) {
                mma_tf32(acc[t][0], af[t], bt[0][0], bt[0][2]);
                mma_tf32(acc[t][1], af[t], bt[0][1], bt[0][3]);
                mma_tf32(acc[t][2], af[t], bt[1][0], bt[1][2]);
                mma_tf32(acc[t][3], af[t], bt[1][1], bt[1][3]);
            }
        }
        __syncthreads();
    }

    const int r = lane >> 2;
    const int cq = (lane & 3) << 1;
#pragma unroll
    for (int t = 0; t < 4; t++) {
        const int row = row0 + wm * 64 + t * 16 + r;
#pragma unroll
        for (int nt = 0; nt < 4; nt++) {
            const int col = col0 + wn * 32 + nt * 8 + cq;
            float2 v0 = make_float2(acc[t][nt][0], acc[t][nt][1]);
            float2 v1 = make_float2(acc[t][nt][2], acc[t][nt][3]);
            if (EPI == 1 || EPI == 2) {
                float b0 = bias[col], b1 = bias[col + 1];
                v0.x += b0; v0.y += b1; v1.x += b0; v1.y += b1;
            }
            if (EPI == 2) {
                float a0 = alpha[col], a1 = alpha[col + 1];
                v0.x = (v0.x >= 0.f) ? v0.x : a0 * v0.x;
                v0.y = (v0.y >= 0.f) ? v0.y : a1 * v0.y;
                v1.x = (v1.x >= 0.f) ? v1.x : a0 * v1.x;
                v1.y = (v1.y >= 0.f) ? v1.y : a1 * v1.y;
            }
            v0.x = rnd32(v0.x); v0.y = rnd32(v0.y);
            v1.x = rnd32(v1.x); v1.y = rnd32(v1.y);
            *(float2*)(C + (size_t)row * ldc + col)       = v0;
            *(float2*)(C + (size_t)(row + 8) * ldc + col) = v1;
        }
    }
}

// ======== fused flash attention (Q fragments preloaded to registers) ========
#define QS_OFF  0u
#define KS_OFF  8448u
#define KS_LEN  4224u
#define VS_OFF  16896u
#define VS_LEN  4352u
#define PS_OFF  25600u
#define FLASH_SMEM  111616   // bytes -> 2 CTAs/SM

__global__ __launch_bounds__(128)
void k_flash(const int* __restrict__ adjs) {
    extern __shared__ __align__(16) char dynsmem[];
    float* smemf = (float*)dynsmem;
    const uint32_t sb = smem_u32(dynsmem);
    const int tid = threadIdx.x, lane = tid & 31, wid = tid >> 5;
    const int fr = lane >> 2, fc = lane & 3;
    const int z = blockIdx.y, b = z >> 2, h = z & 3;
    const int q0 = blockIdx.x * 64;
    const float* Qg = g_qkv + ((size_t)b * NSEQ + q0) * QKVLD + h * DHEAD;
    const float* Kg = g_qkv + (size_t)b * NSEQ * QKVLD + 512 + h * DHEAD;
    const float* Vg = g_qkv + (size_t)b * NSEQ * QKVLD + 1024 + h * DHEAD;
    const int* adj = adjs + (size_t)b * NSEQ * NSEQ;
    const int r_lo = wid * 16 + fr;
    float* Pw = smemf + PS_OFF + wid * 576;   // [16][36] per warp

    // stage Q (64 rows x 32 float4)
#pragma unroll
    for (int u = 0; u < 16; u++) {
        int idx = tid + 128 * u;
        int r = idx >> 5, cg = idx & 31;
        float4 v = *(const float4*)(Qg + (size_t)r * QKVLD + 4 * cg);
        *(float4*)(smemf + QS_OFF + r * 132 + 4 * cg) = v;
    }
    __syncthreads();   // Q visible block-wide

    // preload Q fragments for all 16 k8 steps (tile-invariant) — 64 regs
    unsigned qf[16][4];
#pragma unroll
    for (int k8 = 0; k8 < 16; k8++) {
        const int c = k8 * 8 + fc;
        qf[k8][0] = lds32(sb + 4 * (QS_OFF + (r_lo)     * 132 + c));
        qf[k8][1] = lds32(sb + 4 * (QS_OFF + (r_lo + 8) * 132 + c));
        qf[k8][2] = lds32(sb + 4 * (QS_OFF + (r_lo)     * 132 + c + 4));
        qf[k8][3] = lds32(sb + 4 * (QS_OFF + (r_lo + 8) * 132 + c + 4));
    }

    auto stage_kv = [&](int it, int s) {
        const int k0 = it << 5;
        const uint32_t kO = KS_OFF + s * KS_LEN;
        const uint32_t vO = VS_OFF + s * VS_LEN;
#pragma unroll
        for (int u = 0; u < 8; u++) {
            int idx = tid + 128 * u;
            int r = idx >> 5, cg = idx & 31;
            CP16(sb + 4 * (kO + r * 132 + 4 * cg), Kg + (size_t)(k0 + r) * QKVLD + 4 * cg);
            CP16(sb + 4 * (vO + r * 136 + 4 * cg), Vg + (size_t)(k0 + r) * QKVLD + 4 * cg);
        }
    };

    float acc_o[16][4];
#pragma unroll
    for (int nt = 0; nt < 16; nt++)
#pragma unroll
        for (int j = 0; j < 4; j++) acc_o[nt][j] = 0.f;
    float m0 = -3.4e38f, m1 = -3.4e38f, l0 = 0.f, l1 = 0.f;
    const float rs = 0.08838834764831845f;

    const int T = NSEQ / 32;
    stage_kv(0, 0);
    CP_COMMIT();

    for (int it = 0; it < T; it++) {
        const int s = it & 1;
        if (it + 1 < T) {
            stage_kv(it + 1, s ^ 1);
            CP_COMMIT();
            CP_WAIT(1);
        } else {
            CP_WAIT(0);
        }
        __syncthreads();
        const uint32_t kO = KS_OFF + s * KS_LEN;
        const uint32_t vO = VS_OFF + s * VS_LEN;

        float s_[4][4];
#pragma unroll
        for (int nt = 0; nt < 4; nt++)
#pragma unroll
            for (int j = 0; j < 4; j++) s_[nt][j] = 0.f;
#pragma unroll
        for (int k8 = 0; k8 < 16; k8++) {
            const int c = k8 * 8 + fc;
#pragma unroll
            for (int nt = 0; nt < 4; nt++) {
                const int n = nt * 8 + fr;
                mma_tf32(s_[nt], qf[k8],
                         lds32(sb + 4 * (kO + n * 132 + c)),
                         lds32(sb + 4 * (kO + n * 132 + c + 4)));
            }
        }

        const int k0 = it << 5;
        float mx0 = -3.4e38f, mx1 = -3.4e38f;
#pragma unroll
        for (int nt = 0; nt < 4; nt++) {
            const int col = k0 + nt * 8 + 2 * fc;
            int2 ma = *(const int2*)(adj + (size_t)(q0 + r_lo) * NSEQ + col);
            int2 mb = *(const int2*)(adj + (size_t)(q0 + r_lo + 8) * NSEQ + col);
            s_[nt][0] = ma.x ? s_[nt][0] * rs : -1e9f;
            s_[nt][1] = ma.y ? s_[nt][1] * rs : -1e9f;
            s_[nt][2] = mb.x ? s_[nt][2] * rs : -1e9f;
            s_[nt][3] = mb.y ? s_[nt][3] * rs : -1e9f;
            mx0 = fmaxf(mx0, fmaxf(s_[nt][0], s_[nt][1]));
            mx1 = fmaxf(mx1, fmaxf(s_[nt][2], s_[nt][3]));
        }
        mx0 = fmaxf(mx0, __shfl_xor_sync(~0u, mx0, 1));
        mx0 = fmaxf(mx0, __shfl_xor_sync(~0u, mx0, 2));
        mx1 = fmaxf(mx1, __shfl_xor_sync(~0u, mx1, 1));
        mx1 = fmaxf(mx1, __shfl_xor_sync(~0u, mx1, 2));
        const float mn0 = fmaxf(m0, mx0), mn1 = fmaxf(m1, mx1);
        const float sc0 = __expf(m0 - mn0), sc1 = __expf(m1 - mn1);
        m0 = mn0; m1 = mn1;

        float sum0 = 0.f, sum1 = 0.f;
#pragma unroll
        for (int nt = 0; nt < 4; nt++) {
            s_[nt][0] = __expf(s_[nt][0] - mn0);
            s_[nt][1] = __expf(s_[nt][1] - mn0);
            s_[nt][2] = __expf(s_[nt][2] - mn1);
            s_[nt][3] = __expf(s_[nt][3] - mn1);
            sum0 += s_[nt][0] + s_[nt][1];
            sum1 += s_[nt][2] + s_[nt][3];
            const int pc = nt * 8 + 2 * fc;
            Pw[fr * 36 + pc]           = s_[nt][0];
            Pw[fr * 36 + pc + 1]       = s_[nt][1];
            Pw[(fr + 8) * 36 + pc]     = s_[nt][2];
            Pw[(fr + 8) * 36 + pc + 1] = s_[nt][3];
        }
        sum0 += __shfl_xor_sync(~0u, sum0, 1);
        sum0 += __shfl_xor_sync(~0u, sum0, 2);
        sum1 += __shfl_xor_sync(~0u, sum1, 1);
        sum1 += __shfl_xor_sync(~0u, sum1, 2);
        l0 = l0 * sc0 + sum0;
        l1 = l1 * sc1 + sum1;
        __syncwarp();

#pragma unroll
        for (int nt = 0; nt < 16; nt++) {
            acc_o[nt][0] *= sc0; acc_o[nt][1] *= sc0;
            acc_o[nt][2] *= sc1; acc_o[nt][3] *= sc1;
        }

#pragma unroll
        for (int k8 = 0; k8 < 4; k8++) {
            const int c = k8 * 8 + fc;
            unsigned af[4];
            af[0] = f2tf32(Pw[fr * 36 + c]);
            af[1] = f2tf32(Pw[(fr + 8) * 36 + c]);
            af[2] = f2tf32(Pw[fr * 36 + c + 4]);
            af[3] = f2tf32(Pw[(fr + 8) * 36 + c + 4]);
#pragma unroll
            for (int nt = 0; nt < 16; nt++) {
                const int n = nt * 8 + fr;
                mma_tf32(acc_o[nt], af,
                         lds32(sb + 4 * (vO + c * 136 + n)),
                         lds32(sb + 4 * (vO + (c + 4) * 136 + n)));
            }
        }
        __syncthreads();
    }

    const float inv0 = 1.f / l0, inv1 = 1.f / l1;
    float* Og = g_q + ((size_t)b * NSEQ + q0) * HH + h * DHEAD;
#pragma unroll
    for (int nt = 0; nt < 16; nt++) {
        const int col = nt * 8 + 2 * fc;
        float2 lo = make_float2(rnd32(acc_o[nt][0] * inv0), rnd32(acc_o[nt][1] * inv0));
        float2 hi = make_float2(rnd32(acc_o[nt][2] * inv1), rnd32(acc_o[nt][3] * inv1));
        *(float2*)(Og + (size_t)(r_lo)     * HH + col) = lo;
        *(float2*)(Og + (size_t)(r_lo + 8) * HH + col) = hi;
    }
}

// -------- all-weights transpose, one launch (z = layer*6 + which) --------
__global__ void k_tr_all(const float* __restrict__ Wq, const float* __restrict__ Wk,
                         const float* __restrict__ Wv, const float* __restrict__ Wo,
                         const float* __restrict__ W1, const float* __restrict__ W2,
                         float* __restrict__ pwt) {
    __shared__ float t[32][33];
    const int z = blockIdx.z, j = z / 6, w = z % 6;
    const float* src; float* dst; int R, Cc;
    float* base = pwt + (size_t)j * 3145728;
    switch (w) {
        case 0: src = Wq + (size_t)j * HH * HH;  dst = base;           R = HH;  Cc = HH;  break;
        case 1: src = Wk + (size_t)j * HH * HH;  dst = base + 262144;  R = HH;  Cc = HH;  break;
        case 2: src = Wv + (size_t)j * HH * HH;  dst = base + 524288;  R = HH;  Cc = HH;  break;
        case 3: src = Wo + (size_t)j * HH * HH;  dst = base + 786432;  R = HH;  Cc = HH;  break;
        case 4: src = W1 + (size_t)j * HH * FFD; dst = base + 1048576; R = HH;  Cc = FFD; break;
        default: src = W2 + (size_t)j * FFD * HH; dst = base + 2097152; R = FFD; Cc = HH; break;
    }
    const int c0 = blockIdx.x * 32, r0 = blockIdx.y * 32;
    if (c0 >= Cc || r0 >= R) return;
    const int tx = threadIdx.x, ty = threadIdx.y;
#pragma unroll
    for (int i = 0; i < 4; i++)
        t[ty + 8 * i][tx] = src[(size_t)(r0 + ty + 8 * i) * Cc + c0 + tx];
    __syncthreads();
#pragma unroll
    for (int i = 0; i < 4; i++)
        dst[(size_t)(c0 + ty + 8 * i) * R + r0 + tx] = rnd32(t[tx][ty + 8 * i]);
}

// -------- concat qkv biases --------
__global__ void k_bcat(const float* __restrict__ bq, const float* __restrict__ bk,
                       const float* __restrict__ bv) {
    int i = blockIdx.x * 256 + threadIdx.x;
    if (i >= PP * QKVLD) return;
    int j = i / QKVLD, c = i % QKVLD;
    const float* src = (c < 512) ? bq : ((c < 1024) ? bk : bv);
    g_bcat[i] = src[j * HH + (c & 511)];
}

// -------- build x = concat(vents, renc_w[rels]) (tf32-rounded) --------
__global__ void k_build_x(const float* __restrict__ vents,
                          const float* __restrict__ renc,
                          const int*   __restrict__ rels) {
    int idx = blockIdx.x * blockDim.x + threadIdx.x;
    const int H4 = HH / 4;
    if (idx >= BB * NSEQ * H4) return;
    int hv = idx % H4;
    int n  = (idx / H4) % NSEQ;
    int b  = idx / (H4 * NSEQ);
    float4 val;
    if (n < EE) {
        val = ((const float4*)vents)[(size_t)(b * EE + n) * H4 + hv];
    } else {
        int r = rels[b * RR + (n - EE)];
        val = ((const float4*)renc)[(size_t)r * H4 + hv];
    }
    val.x = rnd32(val.x); val.y = rnd32(val.y);
    val.z = rnd32(val.z); val.w = rnd32(val.w);
    ((float4*)g_x)[idx] = val;
}

// -------- layernorm (optional residual), warp per row --------
__global__ __launch_bounds__(256)
void k_ln(const float* __restrict__ X, const float* __restrict__ Rres,
          const float* __restrict__ g, const float* __restrict__ bsh,
          float* __restrict__ out) {
    const int row  = blockIdx.x * 8 + (threadIdx.x >> 5);
    const int lane = threadIdx.x & 31;
    const float4* xr = (const float4*)(X + (size_t)row * HH);
    float4 v[4];
    float sum = 0.f, sq = 0.f;
#pragma unroll
    for (int i = 0; i < 4; i++) {
        float4 a = xr[lane + 32 * i];
        if (Rres) {
            float4 r = ((const float4*)(Rres + (size_t)row * HH))[lane + 32 * i];
            a.x += r.x; a.y += r.y; a.z += r.z; a.w += r.w;
        }
        v[i] = a;
        sum += a.x + a.y + a.z + a.w;
        sq  += a.x * a.x + a.y * a.y + a.z * a.z + a.w * a.w;
    }
#pragma unroll
    for (int o = 16; o; o >>= 1) {
        sum += __shfl_xor_sync(~0u, sum, o);
        sq  += __shfl_xor_sync(~0u, sq,  o);
    }
    const float mu   = sum * (1.f / HH);
    const float var  = sq * (1.f / HH) - mu * mu;
    const float rstd = rsqrtf(var + 1e-5f);
    float4* op = (float4*)(out + (size_t)row * HH);
#pragma unroll
    for (int i = 0; i < 4; i++) {
        int c4 = lane + 32 * i;
        float4 gg = ((const float4*)g)[c4];
        float4 bb = ((const float4*)bsh)[c4];
        float4 a = v[i];
        a.x = rnd32((a.x - mu) * rstd * gg.x + bb.x);
        a.y = rnd32((a.y - mu) * rstd * gg.y + bb.y);
        a.z = rnd32((a.z - mu) * rstd * gg.z + bb.z);
        a.w = rnd32((a.w - mu) * rstd * gg.w + bb.w);
        op[c4] = a;
    }
}

// -------- output assembly: [glob | gents | emask] --------
__global__ void k_out(float* __restrict__ out) {
    const size_t GENTS = (size_t)BB * NSEQ * HH;
    size_t i = (size_t)blockIdx.x * 256 + threadIdx.x;
    if (i < (size_t)BB * HH) {
        size_t b = i / HH, hc = i % HH;
        out[i] = g_x[b * NSEQ * HH + (size_t)EE * HH + hc];
    }
    if (i < GENTS) out[(size_t)BB * HH + i] = g_x[i];
    if (i < (size_t)BB * NSEQ) out[(size_t)BB * HH + GENTS + i] = 1.0f;
}

extern "C" void kernel_launch(void* const* d_in, const int* in_sizes, int n_in,
                              void* d_out, int out_size) {
    int s = (n_in >= 22) ? 1 : 0;
    const int*   adjs  = (const int*)d_in[0];
    const int*   rels  = (const int*)d_in[1];
    const float* vents = (const float*)d_in[2];
    const float* renc  = (const float*)d_in[3 + s];
    const float* Wq = (const float*)d_in[4 + s];
    const float* Wk = (const float*)d_in[5 + s];
    const float* Wv = (const float*)d_in[6 + s];
    const float* Wo = (const float*)d_in[7 + s];
    const float* W1 = (const float*)d_in[8 + s];
    const float* W2 = (const float*)d_in[9 + s];
    const float* bq = (const float*)d_in[10 + s];
    const float* bk = (const float*)d_in[11 + s];
    const float* bv = (const float*)d_in[12 + s];
    const float* bo = (const float*)d_in[13 + s];
    const float* b1 = (const float*)d_in[14 + s];
    const float* b2 = (const float*)d_in[15 + s];
    const float* ln1g = (const float*)d_in[16 + s];
    const float* ln1b = (const float*)d_in[17 + s];
    const float* ln2g = (const float*)d_in[18 + s];
    const float* ln2b = (const float*)d_in[19 + s];
    const float* pa   = (const float*)d_in[20 + s];

    float *px, *pqkv, *pq, *pk, *pt, *pf, *pwt, *pbc;
    cudaGetSymbolAddress((void**)&px, g_x);
    cudaGetSymbolAddress((void**)&pqkv, g_qkv);
    cudaGetSymbolAddress((void**)&pq, g_q);
    cudaGetSymbolAddress((void**)&pk, g_k);
    cudaGetSymbolAddress((void**)&pt, g_t);
    cudaGetSymbolAddress((void**)&pf, g_f);
    cudaGetSymbolAddress((void**)&pwt, g_wt);
    cudaGetSymbolAddress((void**)&pbc, g_bcat);

    cudaFuncSetAttribute(k_mm<0>, cudaFuncAttributeMaxDynamicSharedMemorySize, SMEM_DYN);
    cudaFuncSetAttribute(k_mm<1>, cudaFuncAttributeMaxDynamicSharedMemorySize, SMEM_DYN);
    cudaFuncSetAttribute(k_mm<2>, cudaFuncAttributeMaxDynamicSharedMemorySize, SMEM_DYN);
    cudaFuncSetAttribute(k_flash, cudaFuncAttributeMaxDynamicSharedMemorySize, FLASH_SMEM);

    k_build_x<<<(BB * NSEQ * (HH / 4) + 255) / 256, 256>>>(vents, renc, rels);
    k_tr_all<<<dim3(64, 64, 12), dim3(32, 8)>>>(Wq, Wk, Wv, Wo, W1, W2, pwt);
    k_bcat<<<(PP * QKVLD + 255) / 256, 256>>>(bq, bk, bv);

    const size_t LSTR = 3145728;
    for (int j = 0; j < PP; j++) {
        float* base = pwt + j * LSTR;
        // fused QKV: C[8192,1536] = x @ [Wq|Wk|Wv]^T
        k_mm<1><<<dim3(QKVLD / 128, MTOK / 128), 256, SMEM_DYN>>>(
            px, HH, base, HH, pqkv, QKVLD, HH, pbc + j * QKVLD, nullptr);

        k_flash<<<dim3(NSEQ / 64, BB * NHEAD), 128, FLASH_SMEM>>>(adjs);   // attn out -> g_q

        k_mm<1><<<dim3(HH / 128, MTOK / 128), 256, SMEM_DYN>>>(
            pq, HH, base + 786432, HH, pk, HH, HH, bo + j * HH, nullptr);
        k_ln<<<MTOK / 8, 256>>>(pk, nullptr, ln1g + j * HH, ln1b + j * HH, pt);

        k_mm<2><<<dim3(FFD / 128, MTOK / 128), 256, SMEM_DYN>>>(
            pt, HH, base + 1048576, HH, pf, FFD, HH, b1 + j * FFD, pa + j * FFD);
        k_mm<1><<<dim3(HH / 128, MTOK / 128), 256, SMEM_DYN>>>(
            pf, FFD, base + 2097152, FFD, pk, HH, FFD, b2 + j * HH, nullptr);

        k_ln<<<MTOK / 8, 256>>>(pk, pt, ln2g + j * HH, ln2b + j * HH, px);
    }

    k_out<<<(BB * NSEQ * HH + 255) / 256, 256>>>((float*)d_out);
}

// round 16
// speedup vs baseline: 1.6012x; 1.4536x over previous
#include <cuda_runtime.h>
#include <cstdint>

// Problem constants
#define BB     4
#define NSEQ   2048
#define EE     1600
#define RR     448
#define HH     512
#define NHEAD  4
#define DHEAD  128
#define PP     2
#define FFD    2048
#define MTOK   (BB*NSEQ)
#define QKVLD  1536

// -------- scratch (device globals; no allocation allowed) --------
__device__ float g_x[(size_t)BB*NSEQ*HH];
__device__ float g_qkv[(size_t)BB*NSEQ*QKVLD];
__device__ float g_q[(size_t)BB*NSEQ*HH];
__device__ float g_k[(size_t)BB*NSEQ*HH];
__device__ float g_t[(size_t)BB*NSEQ*HH];
__device__ float g_f[(size_t)BB*NSEQ*FFD];
__device__ float g_wt[(size_t)PP*3145728];            // transposed weights
__device__ float g_bcat[PP*QKVLD];                    // concat qkv bias
__device__ unsigned g_adjb[(size_t)BB*NSEQ*(NSEQ/32)]; // adjacency bitmask

// ---------------- helpers ----------------
__device__ __forceinline__ unsigned f2tf32(float x) {
    unsigned r; asm("cvt.rna.tf32.f32 %0, %1;" : "=r"(r) : "f"(x)); return r;
}
__device__ __forceinline__ float rnd32(float x) {
    return __uint_as_float(f2tf32(x));
}
__device__ __forceinline__ uint32_t smem_u32(const void* p) {
    uint32_t a;
    asm("{ .reg .u64 t; cvta.to.shared.u64 t, %1; cvt.u32.u64 %0, t; }" : "=r"(a) : "l"(p));
    return a;
}
__device__ __forceinline__ unsigned lds32(uint32_t a) {
    unsigned v; asm("ld.shared.b32 %0, [%1];" : "=r"(v) : "r"(a)); return v;
}
// ldmatrix x4: four 8x8 b16 tiles -> 4 regs/lane (tf32 fragment gather)
__device__ __forceinline__ void ldsm4(unsigned* r, uint32_t a) {
    asm volatile("ldmatrix.sync.aligned.m8n8.x4.shared.b16 {%0,%1,%2,%3}, [%4];"
                 : "=r"(r[0]), "=r"(r[1]), "=r"(r[2]), "=r"(r[3]) : "r"(a));
}
#define SWZ128(o) ((o) ^ (((o) >> 3) & 0x70))

__device__ __forceinline__ void mma_tf32(float* d, const unsigned* a,
                                         unsigned b0, unsigned b1) {
    asm volatile("mma.sync.aligned.m16n8k8.row.col.f32.tf32.tf32.f32 "
                 "{%0,%1,%2,%3}, {%4,%5,%6,%7}, {%8,%9}, {%0,%1,%2,%3};"
                 : "+f"(d[0]), "+f"(d[1]), "+f"(d[2]), "+f"(d[3])
                 : "r"(a[0]), "r"(a[1]), "r"(a[2]), "r"(a[3]),
                   "r"(b0), "r"(b1));
}

#define CP16(d, s)   asm volatile("cp.async.cg.shared.global [%0], [%1], 16;" :: "r"(d), "l"(s))
#define CP_COMMIT()  asm volatile("cp.async.commit_group;")
#define CP_WAIT(n)   asm volatile("cp.async.wait_group %0;" :: "n"(n))

#define STAGE_SZ   32768     // GEMM: A(16KB, 128x32 f32 SW128) + B(16KB)
#define SMEM_DYN   (2*STAGE_SZ)

// ======== pipelined tf32 mma.sync GEMM (EXACT R12 version — frozen) ========
template<int EPI>   // 0 none, 1 +bias, 2 +bias+prelu
__global__ __launch_bounds__(256, 2)
void k_mm(const float* __restrict__ A, int lda,
          const float* __restrict__ B, int ldb,
          float* __restrict__ C, int ldc, int K,
          const float* __restrict__ bias,
          const float* __restrict__ alpha)
{
    extern __shared__ __align__(1024) char dynsmem[];
    const uint32_t sb = smem_u32(dynsmem);
    const int tid = threadIdx.x, lane = tid & 31, wid = tid >> 5;
    const int wm = wid & 1, wn = wid >> 1;
    const int row0 = blockIdx.y * 128, col0 = blockIdx.x * 128;

    auto copy_tile = [&](int it, int s) {
        const uint32_t a_s = sb + s * STAGE_SZ;
        const uint32_t b_s = a_s + 16384;
        const int k0 = it << 5;
#pragma unroll
        for (int u = 0; u < 4; u++) {
            int idx = tid + 256 * u;
            int r = idx >> 3, c16 = (idx & 7) << 4;
            uint32_t sw = SWZ128((r << 7) + c16);
            CP16(a_s + sw, A + (size_t)(row0 + r) * lda + k0 + (c16 >> 2));
            CP16(b_s + sw, B + (size_t)(col0 + r) * ldb + k0 + (c16 >> 2));
        }
    };

    float acc[4][4][4];
#pragma unroll
    for (int t = 0; t < 4; t++)
#pragma unroll
        for (int nt = 0; nt < 4; nt++)
#pragma unroll
            for (int r = 0; r < 4; r++) acc[t][nt][r] = 0.f;

    const int T = K >> 5;
    copy_tile(0, 0);
    CP_COMMIT();

    const int li = lane & 15;
    const int chb = ((lane >> 4) << 4);       // byte offset of col-half

    for (int it = 0; it < T; it++) {
        const int s = it & 1;
        if (it + 1 < T) {
            copy_tile(it + 1, s ^ 1);
            CP_COMMIT();
            CP_WAIT(1);
        } else {
            CP_WAIT(0);
        }
        __syncthreads();

        const uint32_t a_s = sb + s * STAGE_SZ;
        const uint32_t b_s = a_s + 16384;
        const uint32_t aR0 = a_s + ((wm * 64 + li) << 7);
        const uint32_t bR0 = b_s + ((wn * 32 + li) << 7);
#pragma unroll
        for (int k8 = 0; k8 < 4; k8++) {
            const uint32_t cb = (k8 << 5) + chb;   // byte col offset
            unsigned af[4][4], bt[2][4];
#pragma unroll
            for (int t = 0; t < 4; t++)
                ldsm4(af[t], SWZ128((aR0 + (t << 11)) + cb));
#pragma unroll
            for (int p = 0; p < 2; p++)
                ldsm4(bt[p], SWZ128((bR0 + (p << 11)) + cb));
#pragma unroll
            for (int t = 0; t < 4; t++) {
                mma_tf32(acc[t][0], af[t], bt[0][0], bt[0][2]);
                mma_tf32(acc[t][1], af[t], bt[0][1], bt[0][3]);
                mma_tf32(acc[t][2], af[t], bt[1][0], bt[1][2]);
                mma_tf32(acc[t][3], af[t], bt[1][1], bt[1][3]);
            }
        }
        __syncthreads();
    }

    const int r = lane >> 2;
    const int cq = (lane & 3) << 1;
#pragma unroll
    for (int t = 0; t < 4; t++) {
        const int row = row0 + wm * 64 + t * 16 + r;
#pragma unroll
        for (int nt = 0; nt < 4; nt++) {
            const int col = col0 + wn * 32 + nt * 8 + cq;
            float2 v0 = make_float2(acc[t][nt][0], acc[t][nt][1]);
            float2 v1 = make_float2(acc[t][nt][2], acc[t][nt][3]);
            if (EPI == 1 || EPI == 2) {
                float b0 = bias[col], b1 = bias[col + 1];
                v0.x += b0; v0.y += b1; v1.x += b0; v1.y += b1;
            }
            if (EPI == 2) {
                float a0 = alpha[col], a1 = alpha[col + 1];
                v0.x = (v0.x >= 0.f) ? v0.x : a0 * v0.x;
                v0.y = (v0.y >= 0.f) ? v0.y : a1 * v0.y;
                v1.x = (v1.x >= 0.f) ? v1.x : a0 * v1.x;
                v1.y = (v1.y >= 0.f) ? v1.y : a1 * v1.y;
            }
            v0.x = rnd32(v0.x); v0.y = rnd32(v0.y);
            v1.x = rnd32(v1.x); v1.y = rnd32(v1.y);
            *(float2*)(C + (size_t)row * ldc + col)       = v0;
            *(float2*)(C + (size_t)(row + 8) * ldc + col) = v1;
        }
    }
}

// -------- adjacency -> bitmask (one warp per row; ballot pack) --------
__global__ void k_adjbits(const int* __restrict__ adjs) {
    const int row  = blockIdx.x * 8 + (threadIdx.x >> 5);   // b*NSEQ + n
    const int lane = threadIdx.x & 31;
    const int* src = adjs + (size_t)row * NSEQ;
    unsigned* dst  = g_adjb + (size_t)row * (NSEQ / 32);
    for (int w = 0; w < NSEQ / 32; w++) {
        int v = src[w * 32 + lane];
        unsigned bits = __ballot_sync(~0u, v != 0);
        if (lane == 0) dst[w] = bits;
    }
}

// ======== fused flash attention (R12 body; mask via bitmask words) ========
#define QS_OFF  0u
#define KS_OFF  8448u
#define KS_LEN  4224u
#define VS_OFF  16896u
#define VS_LEN  4352u
#define PS_OFF  25600u
#define FLASH_SMEM  111616   // bytes -> 2 CTAs/SM

__global__ __launch_bounds__(128)
void k_flash() {
    extern __shared__ __align__(16) char dynsmem[];
    float* smemf = (float*)dynsmem;
    const uint32_t sb = smem_u32(dynsmem);
    const int tid = threadIdx.x, lane = tid & 31, wid = tid >> 5;
    const int fr = lane >> 2, fc = lane & 3;
    const int z = blockIdx.y, b = z >> 2, h = z & 3;
    const int q0 = blockIdx.x * 64;
    const float* Qg = g_qkv + ((size_t)b * NSEQ + q0) * QKVLD + h * DHEAD;
    const float* Kg = g_qkv + (size_t)b * NSEQ * QKVLD + 512 + h * DHEAD;
    const float* Vg = g_qkv + (size_t)b * NSEQ * QKVLD + 1024 + h * DHEAD;
    const unsigned* adjb = g_adjb + ((size_t)b * NSEQ + q0) * (NSEQ / 32);
    const int r_lo = wid * 16 + fr;
    float* Pw = smemf + PS_OFF + wid * 576;   // [16][36] per warp

#pragma unroll
    for (int u = 0; u < 16; u++) {
        int idx = tid + 128 * u;
        int r = idx >> 5, cg = idx & 31;
        float4 v = *(const float4*)(Qg + (size_t)r * QKVLD + 4 * cg);
        *(float4*)(smemf + QS_OFF + r * 132 + 4 * cg) = v;
    }

    auto stage_kv = [&](int it, int s) {
        const int k0 = it << 5;
        const uint32_t kO = KS_OFF + s * KS_LEN;
        const uint32_t vO = VS_OFF + s * VS_LEN;
#pragma unroll
        for (int u = 0; u < 8; u++) {
            int idx = tid + 128 * u;
            int r = idx >> 5, cg = idx & 31;
            CP16(sb + 4 * (kO + r * 132 + 4 * cg), Kg + (size_t)(k0 + r) * QKVLD + 4 * cg);
            CP16(sb + 4 * (vO + r * 136 + 4 * cg), Vg + (size_t)(k0 + r) * QKVLD + 4 * cg);
        }
    };

    float acc_o[16][4];
#pragma unroll
    for (int nt = 0; nt < 16; nt++)
#pragma unroll
        for (int j = 0; j < 4; j++) acc_o[nt][j] = 0.f;
    float m0 = -3.4e38f, m1 = -3.4e38f, l0 = 0.f, l1 = 0.f;
    const float rs = 0.08838834764831845f;

    const int T = NSEQ / 32;
    stage_kv(0, 0);
    CP_COMMIT();

    for (int it = 0; it < T; it++) {
        const int s = it & 1;
        if (it + 1 < T) {
            stage_kv(it + 1, s ^ 1);
            CP_COMMIT();
            CP_WAIT(1);
        } else {
            CP_WAIT(0);
        }
        __syncthreads();
        const uint32_t kO = KS_OFF + s * KS_LEN;
        const uint32_t vO = VS_OFF + s * VS_LEN;

        float s_[4][4];
#pragma unroll
        for (int nt = 0; nt < 4; nt++)
#pragma unroll
            for (int j = 0; j < 4; j++) s_[nt][j] = 0.f;
#pragma unroll
        for (int k8 = 0; k8 < 16; k8++) {
            const int c = k8 * 8 + fc;
            unsigned af[4];
            af[0] = lds32(sb + 4 * (QS_OFF + (r_lo)     * 132 + c));
            af[1] = lds32(sb + 4 * (QS_OFF + (r_lo + 8) * 132 + c));
            af[2] = lds32(sb + 4 * (QS_OFF + (r_lo)     * 132 + c + 4));
            af[3] = lds32(sb + 4 * (QS_OFF + (r_lo + 8) * 132 + c + 4));
#pragma unroll
            for (int nt = 0; nt < 4; nt++) {
                const int n = nt * 8 + fr;
                mma_tf32(s_[nt], af,
                         lds32(sb + 4 * (kO + n * 132 + c)),
                         lds32(sb + 4 * (kO + n * 132 + c + 4)));
            }
        }

        // ---- mask via bitmask words + scale, row max (quad shfl) ----
        const unsigned w0 = adjb[(size_t)(r_lo)     * (NSEQ / 32) + it];
        const unsigned w1 = adjb[(size_t)(r_lo + 8) * (NSEQ / 32) + it];
        float mx0 = -3.4e38f, mx1 = -3.4e38f;
#pragma unroll
        for (int nt = 0; nt < 4; nt++) {
            const int bit = nt * 8 + 2 * fc;
            s_[nt][0] = ((w0 >> bit) & 1u)       ? s_[nt][0] * rs : -1e9f;
            s_[nt][1] = ((w0 >> (bit + 1)) & 1u) ? s_[nt][1] * rs : -1e9f;
            s_[nt][2] = ((w1 >> bit) & 1u)       ? s_[nt][2] * rs : -1e9f;
            s_[nt][3] = ((w1 >> (bit + 1)) & 1u) ? s_[nt][3] * rs : -1e9f;
            mx0 = fmaxf(mx0, fmaxf(s_[nt][0], s_[nt][1]));
            mx1 = fmaxf(mx1, fmaxf(s_[nt][2], s_[nt][3]));
        }
        mx0 = fmaxf(mx0, __shfl_xor_sync(~0u, mx0, 1));
        mx0 = fmaxf(mx0, __shfl_xor_sync(~0u, mx0, 2));
        mx1 = fmaxf(mx1, __shfl_xor_sync(~0u, mx1, 1));
        mx1 = fmaxf(mx1, __shfl_xor_sync(~0u, mx1, 2));
        const float mn0 = fmaxf(m0, mx0), mn1 = fmaxf(m1, mx1);
        const float sc0 = __expf(m0 - mn0), sc1 = __expf(m1 - mn1);
        m0 = mn0; m1 = mn1;

        float sum0 = 0.f, sum1 = 0.f;
#pragma unroll
        for (int nt = 0; nt < 4; nt++) {
            s_[nt][0] = __expf(s_[nt][0] - mn0);
            s_[nt][1] = __expf(s_[nt][1] - mn0);
            s_[nt][2] = __expf(s_[nt][2] - mn1);
            s_[nt][3] = __expf(s_[nt][3] - mn1);
            sum0 += s_[nt][0] + s_[nt][1];
            sum1 += s_[nt][2] + s_[nt][3];
            const int pc = nt * 8 + 2 * fc;
            Pw[fr * 36 + pc]           = s_[nt][0];
            Pw[fr * 36 + pc + 1]       = s_[nt][1];
            Pw[(fr + 8) * 36 + pc]     = s_[nt][2];
            Pw[(fr + 8) * 36 + pc + 1] = s_[nt][3];
        }
        sum0 += __shfl_xor_sync(~0u, sum0, 1);
        sum0 += __shfl_xor_sync(~0u, sum0, 2);
        sum1 += __shfl_xor_sync(~0u, sum1, 1);
        sum1 += __shfl_xor_sync(~0u, sum1, 2);
        l0 = l0 * sc0 + sum0;
        l1 = l1 * sc1 + sum1;
        __syncwarp();

#pragma unroll
        for (int nt = 0; nt < 16; nt++) {
            acc_o[nt][0] *= sc0; acc_o[nt][1] *= sc0;
            acc_o[nt][2] *= sc1; acc_o[nt][3] *= sc1;
        }

#pragma unroll
        for (int k8 = 0; k8 < 4; k8++) {
            const int c = k8 * 8 + fc;
            unsigned af[4];
            af[0] = f2tf32(Pw[fr * 36 + c]);
            af[1] = f2tf32(Pw[(fr + 8) * 36 + c]);
            af[2] = f2tf32(Pw[fr * 36 + c + 4]);
            af[3] = f2tf32(Pw[(fr + 8) * 36 + c + 4]);
#pragma unroll
            for (int nt = 0; nt < 16; nt++) {
                const int n = nt * 8 + fr;
                mma_tf32(acc_o[nt], af,
                         lds32(sb + 4 * (vO + c * 136 + n)),
                         lds32(sb + 4 * (vO + (c + 4) * 136 + n)));
            }
        }
        __syncthreads();
    }

    const float inv0 = 1.f / l0, inv1 = 1.f / l1;
    float* Og = g_q + ((size_t)b * NSEQ + q0) * HH + h * DHEAD;
#pragma unroll
    for (int nt = 0; nt < 16; nt++) {
        const int col = nt * 8 + 2 * fc;
        float2 lo = make_float2(rnd32(acc_o[nt][0] * inv0), rnd32(acc_o[nt][1] * inv0));
        float2 hi = make_float2(rnd32(acc_o[nt][2] * inv1), rnd32(acc_o[nt][3] * inv1));
        *(float2*)(Og + (size_t)(r_lo)     * HH + col) = lo;
        *(float2*)(Og + (size_t)(r_lo + 8) * HH + col) = hi;
    }
}

// -------- all-weights transpose, one launch (z = layer*6 + which) --------
__global__ void k_tr_all(const float* __restrict__ Wq, const float* __restrict__ Wk,
                         const float* __restrict__ Wv, const float* __restrict__ Wo,
                         const float* __restrict__ W1, const float* __restrict__ W2,
                         float* __restrict__ pwt) {
    __shared__ float t[32][33];
    const int z = blockIdx.z, j = z / 6, w = z % 6;
    const float* src; float* dst; int R, Cc;
    float* base = pwt + (size_t)j * 3145728;
    switch (w) {
        case 0: src = Wq + (size_t)j * HH * HH;  dst = base;           R = HH;  Cc = HH;  break;
        case 1: src = Wk + (size_t)j * HH * HH;  dst = base + 262144;  R = HH;  Cc = HH;  break;
        case 2: src = Wv + (size_t)j * HH * HH;  dst = base + 524288;  R = HH;  Cc = HH;  break;
        case 3: src = Wo + (size_t)j * HH * HH;  dst = base + 786432;  R = HH;  Cc = HH;  break;
        case 4: src = W1 + (size_t)j * HH * FFD; dst = base + 1048576; R = HH;  Cc = FFD; break;
        default: src = W2 + (size_t)j * FFD * HH; dst = base + 2097152; R = FFD; Cc = HH; break;
    }
    const int c0 = blockIdx.x * 32, r0 = blockIdx.y * 32;
    if (c0 >= Cc || r0 >= R) return;
    const int tx = threadIdx.x, ty = threadIdx.y;
#pragma unroll
    for (int i = 0; i < 4; i++)
        t[ty + 8 * i][tx] = src[(size_t)(r0 + ty + 8 * i) * Cc + c0 + tx];
    __syncthreads();
#pragma unroll
    for (int i = 0; i < 4; i++)
        dst[(size_t)(c0 + ty + 8 * i) * R + r0 + tx] = rnd32(t[tx][ty + 8 * i]);
}

// -------- concat qkv biases --------
__global__ void k_bcat(const float* __restrict__ bq, const float* __restrict__ bk,
                       const float* __restrict__ bv) {
    int i = blockIdx.x * 256 + threadIdx.x;
    if (i >= PP * QKVLD) return;
    int j = i / QKVLD, c = i % QKVLD;
    const float* src = (c < 512) ? bq : ((c < 1024) ? bk : bv);
    g_bcat[i] = src[j * HH + (c & 511)];
}

// -------- build x = concat(vents, renc_w[rels]) (tf32-rounded) --------
__global__ void k_build_x(const float* __restrict__ vents,
                          const float* __restrict__ renc,
                          const int*   __restrict__ rels) {
    int idx = blockIdx.x * blockDim.x + threadIdx.x;
    const int H4 = HH / 4;
    if (idx >= BB * NSEQ * H4) return;
    int hv = idx % H4;
    int n  = (idx / H4) % NSEQ;
    int b  = idx / (H4 * NSEQ);
    float4 val;
    if (n < EE) {
        val = ((const float4*)vents)[(size_t)(b * EE + n) * H4 + hv];
    } else {
        int r = rels[b * RR + (n - EE)];
        val = ((const float4*)renc)[(size_t)r * H4 + hv];
    }
    val.x = rnd32(val.x); val.y = rnd32(val.y);
    val.z = rnd32(val.z); val.w = rnd32(val.w);
    ((float4*)g_x)[idx] = val;
}

// -------- layernorm (optional residual), warp per row --------
__global__ __launch_bounds__(256)
void k_ln(const float* __restrict__ X, const float* __restrict__ Rres,
          const float* __restrict__ g, const float* __restrict__ bsh,
          float* __restrict__ out) {
    const int row  = blockIdx.x * 8 + (threadIdx.x >> 5);
    const int lane = threadIdx.x & 31;
    const float4* xr = (const float4*)(X + (size_t)row * HH);
    float4 v[4];
    float sum = 0.f, sq = 0.f;
#pragma unroll
    for (int i = 0; i < 4; i++) {
        float4 a = xr[lane + 32 * i];
        if (Rres) {
            float4 r = ((const float4*)(Rres + (size_t)row * HH))[lane + 32 * i];
            a.x += r.x; a.y += r.y; a.z += r.z; a.w += r.w;
        }
        v[i] = a;
        sum += a.x + a.y + a.z + a.w;
        sq  += a.x * a.x + a.y * a.y + a.z * a.z + a.w * a.w;
    }
#pragma unroll
    for (int o = 16; o; o >>= 1) {
        sum += __shfl_xor_sync(~0u, sum, o);
        sq  += __shfl_xor_sync(~0u, sq,  o);
    }
    const float mu   = sum * (1.f / HH);
    const float var  = sq * (1.f / HH) - mu * mu;
    const float rstd = rsqrtf(var + 1e-5f);
    float4* op = (float4*)(out + (size_t)row * HH);
#pragma unroll
    for (int i = 0; i < 4; i++) {
        int c4 = lane + 32 * i;
        float4 gg = ((const float4*)g)[c4];
        float4 bb = ((const float4*)bsh)[c4];
        float4 a = v[i];
        a.x = rnd32((a.x - mu) * rstd * gg.x + bb.x);
        a.y = rnd32((a.y - mu) * rstd * gg.y + bb.y);
        a.z = rnd32((a.z - mu) * rstd * gg.z + bb.z);
        a.w = rnd32((a.w - mu) * rstd * gg.w + bb.w);
        op[c4] = a;
    }
}

// -------- output assembly: [glob | gents | emask] --------
__global__ void k_out(float* __restrict__ out) {
    const size_t GENTS = (size_t)BB * NSEQ * HH;
    size_t i = (size_t)blockIdx.x * 256 + threadIdx.x;
    if (i < (size_t)BB * HH) {
        size_t b = i / HH, hc = i % HH;
        out[i] = g_x[b * NSEQ * HH + (size_t)EE * HH + hc];
    }
    if (i < GENTS) out[(size_t)BB * HH + i] = g_x[i];
    if (i < (size_t)BB * NSEQ) out[(size_t)BB * HH + GENTS + i] = 1.0f;
}

extern "C" void kernel_launch(void* const* d_in, const int* in_sizes, int n_in,
                              void* d_out, int out_size) {
    int s = (n_in >= 22) ? 1 : 0;
    const int*   adjs  = (const int*)d_in[0];
    const int*   rels  = (const int*)d_in[1];
    const float* vents = (const float*)d_in[2];
    const float* renc  = (const float*)d_in[3 + s];
    const float* Wq = (const float*)d_in[4 + s];
    const float* Wk = (const float*)d_in[5 + s];
    const float* Wv = (const float*)d_in[6 + s];
    const float* Wo = (const float*)d_in[7 + s];
    const float* W1 = (const float*)d_in[8 + s];
    const float* W2 = (const float*)d_in[9 + s];
    const float* bq = (const float*)d_in[10 + s];
    const float* bk = (const float*)d_in[11 + s];
    const float* bv = (const float*)d_in[12 + s];
    const float* bo = (const float*)d_in[13 + s];
    const float* b1 = (const float*)d_in[14 + s];
    const float* b2 = (const float*)d_in[15 + s];
    const float* ln1g = (const float*)d_in[16 + s];
    const float* ln1b = (const float*)d_in[17 + s];
    const float* ln2g = (const float*)d_in[18 + s];
    const float* ln2b = (const float*)d_in[19 + s];
    const float* pa   = (const float*)d_in[20 + s];

    float *px, *pqkv, *pq, *pk, *pt, *pf, *pwt, *pbc;
    cudaGetSymbolAddress((void**)&px, g_x);
    cudaGetSymbolAddress((void**)&pqkv, g_qkv);
    cudaGetSymbolAddress((void**)&pq, g_q);
    cudaGetSymbolAddress((void**)&pk, g_k);
    cudaGetSymbolAddress((void**)&pt, g_t);
    cudaGetSymbolAddress((void**)&pf, g_f);
    cudaGetSymbolAddress((void**)&pwt, g_wt);
    cudaGetSymbolAddress((void**)&pbc, g_bcat);

    cudaFuncSetAttribute(k_mm<0>, cudaFuncAttributeMaxDynamicSharedMemorySize, SMEM_DYN);
    cudaFuncSetAttribute(k_mm<1>, cudaFuncAttributeMaxDynamicSharedMemorySize, SMEM_DYN);
    cudaFuncSetAttribute(k_mm<2>, cudaFuncAttributeMaxDynamicSharedMemorySize, SMEM_DYN);
    cudaFuncSetAttribute(k_flash, cudaFuncAttributeMaxDynamicSharedMemorySize, FLASH_SMEM);

    k_build_x<<<(BB * NSEQ * (HH / 4) + 255) / 256, 256>>>(vents, renc, rels);
    k_tr_all<<<dim3(64, 64, 12), dim3(32, 8)>>>(Wq, Wk, Wv, Wo, W1, W2, pwt);
    k_bcat<<<(PP * QKVLD + 255) / 256, 256>>>(bq, bk, bv);
    k_adjbits<<<(BB * NSEQ) / 8, 256>>>(adjs);

    const size_t LSTR = 3145728;
    for (int j = 0; j < PP; j++) {
        float* base = pwt + j * LSTR;
        // fused QKV: C[8192,1536] = x @ [Wq|Wk|Wv]^T
        k_mm<1><<<dim3(QKVLD / 128, MTOK / 128), 256, SMEM_DYN>>>(
            px, HH, base, HH, pqkv, QKVLD, HH, pbc + j * QKVLD, nullptr);

        k_flash<<<dim3(NSEQ / 64, BB * NHEAD), 128, FLASH_SMEM>>>();   // attn out -> g_q

        k_mm<1><<<dim3(HH / 128, MTOK / 128), 256, SMEM_DYN>>>(
            pq, HH, base + 786432, HH, pk, HH, HH, bo + j * HH, nullptr);
        k_ln<<<MTOK / 8, 256>>>(pk, nullptr, ln1g + j * HH, ln1b + j * HH, pt);

        k_mm<2><<<dim3(FFD / 128, MTOK / 128), 256, SMEM_DYN>>>(
            pt, HH, base + 1048576, HH, pf, FFD, HH, b1 + j * FFD, pa + j * FFD);
        k_mm<1><<<dim3(HH / 128, MTOK / 128), 256, SMEM_DYN>>>(
            pf, FFD, base + 2097152, FFD, pk, HH, FFD, b2 + j * HH, nullptr);

        k_ln<<<MTOK / 8, 256>>>(pk, pt, ln2g + j * HH, ln2b + j * HH, px);
    }

    k_out<<<(BB * NSEQ * HH + 255) / 256, 256>>>((float*)d_out);
}